// round 9
// baseline (speedup 1.0000x reference)
#include <cuda_runtime.h>
#include <cuda_fp16.h>
#include <cstdint>
#include <cstddef>

#define NODE_DIM 128
#define EDGE_DIM 128
#define N_A 512
#define N_B 512
#define M_EDGES (N_A * N_B)

// ---------------------------------------------------------------------------
// Device scratch
// ---------------------------------------------------------------------------
__device__ float g_aproj[N_A * EDGE_DIM];     // nodes_a @ Wa + be1
__device__ float g_bproj[N_B * EDGE_DIM];     // nodes_b @ Wb (fp32)
__device__ __half g_bprojh[N_B * EDGE_DIM];   // fp16 copy for fused epilogue
__device__ float g_suma[N_A * EDGE_DIM];      // accumulated by fused kernel
__device__ float g_sumb[N_B * EDGE_DIM];      // accumulated by sum_b kernel
__device__ float g_Wn1T[NODE_DIM * 2 * NODE_DIM];  // [d][k] transpose of Wn1
__device__ float g_Wn2T[NODE_DIM * NODE_DIM];      // [d][k] transpose of Wn2
// Pre-transposed fp16 weight images: [chunk][n(128)][k(64)]
__device__ __half g_Bimg1[4 * 8192];  // We  (256x128): 4 K-chunks
__device__ __half g_Bimg2[2 * 8192];  // We2 (128x128): 2 K-chunks

// ---------------------------------------------------------------------------
// PTX helpers (compute_80+ only)
// ---------------------------------------------------------------------------
__device__ __forceinline__ uint32_t smem_u32(const void* p) {
    uint32_t a;
    asm("{ .reg .u64 t; cvta.to.shared.u64 t, %1; cvt.u32.u64 %0, t; }" : "=r"(a) : "l"(p));
    return a;
}
__device__ __forceinline__ void ldsm_x4(uint32_t addr, uint32_t* r) {
    asm volatile("ldmatrix.sync.aligned.m8n8.x4.shared.b16 {%0,%1,%2,%3}, [%4];"
                 : "=r"(r[0]), "=r"(r[1]), "=r"(r[2]), "=r"(r[3]) : "r"(addr));
}
__device__ __forceinline__ void mma_f16(float* c, const uint32_t* a, uint32_t b0, uint32_t b1) {
    asm volatile(
        "mma.sync.aligned.m16n8k16.row.col.f32.f16.f16.f32 "
        "{%0,%1,%2,%3}, {%4,%5,%6,%7}, {%8,%9}, {%0,%1,%2,%3};"
        : "+f"(c[0]), "+f"(c[1]), "+f"(c[2]), "+f"(c[3])
        : "r"(a[0]), "r"(a[1]), "r"(a[2]), "r"(a[3]), "r"(b0), "r"(b1));
}
#define CP_ASYNC16(dst, src) \
    asm volatile("cp.async.cg.shared.global [%0], [%1], 16;" :: "r"(dst), "l"(src))
#define CP_COMMIT() asm volatile("cp.async.commit_group;" ::: "memory")
#define CP_WAIT_ALL() asm volatile("cp.async.wait_group 0;" ::: "memory")

// SMEM layout. Padded row stride: 72 fp16 = 144 B (conflict-free ldmatrix).
#define RSTRIDE 144
#define BLK 18432                   /* one [128][72] b16 image */
#define AS_OFF 0                    /* A bufs 0,1 -> later h chunks 0,1   */
#define BS_OFF (2 * BLK)            /* B bufs 0,1 -> later We2 chunks 0,1 */
#define WSUM_OFF (4 * BLK)          /* 8 warps x 64 floats = 2 KB         */
#define SMEM_BYTES (4 * BLK + 2048) /* 75776 -> 2 CTAs/SM                 */

// ---------------------------------------------------------------------------
// init: [0,128) Bimg1; [128,192) Bimg2; [192,704) projections + zero sums;
//       [704,832) Wn1 transpose; [832,896) Wn2 transpose.
// ---------------------------------------------------------------------------
__global__ void __launch_bounds__(256) init_kernel(const float* __restrict__ We1,
                                                   const float* __restrict__ We2,
                                                   const float* __restrict__ na,
                                                   const float* __restrict__ nb,
                                                   const float* __restrict__ be1,
                                                   const float* __restrict__ Wn1,
                                                   const float* __restrict__ Wn2) {
    int blk = blockIdx.x;
    int tid = threadIdx.x;
    if (blk < 128) {
        int eid = blk * 256 + tid;          // [0, 32768)
        int kc = eid >> 13;
        int n = (eid >> 6) & 127;
        int kk = eid & 63;
        float wv = We1[(2 * NODE_DIM + kc * 64 + kk) * EDGE_DIM + n];
        g_Bimg1[(size_t)kc * 8192 + n * 64 + kk] = __float2half_rn(wv);
    } else if (blk < 192) {
        int eid = (blk - 128) * 256 + tid;  // [0, 16384)
        int kc = eid >> 13;
        int n = (eid >> 6) & 127;
        int kk = eid & 63;
        float wv = We2[(kc * 64 + kk) * EDGE_DIM + n];
        g_Bimg2[(size_t)kc * 8192 + n * 64 + kk] = __float2half_rn(wv);
    } else if (blk < 704) {
        __shared__ float x[2][NODE_DIM];
        int sub = tid >> 7;                 // 0/1: node within block
        int i = (blk - 192) * 2 + sub;      // [0, 1024)
        int d = tid & 127;
        const float* src;
        const float* W;
        float* dst;
        float acc;
        if (i < N_A) {
            src = na + i * NODE_DIM;
            dst = g_aproj + i * EDGE_DIM;
            W = We1;
            acc = be1[d];
            g_suma[i * EDGE_DIM + d] = 0.f;
        } else {
            int j = i - N_A;
            src = nb + j * NODE_DIM;
            dst = g_bproj + j * EDGE_DIM;
            W = We1 + NODE_DIM * EDGE_DIM;
            acc = 0.f;
            g_sumb[j * EDGE_DIM + d] = 0.f;
        }
        x[sub][d] = src[d];
        __syncthreads();
#pragma unroll 8
        for (int k = 0; k < NODE_DIM; k++) acc = fmaf(x[sub][k], W[k * EDGE_DIM + d], acc);
        dst[d] = acc;
        if (i >= N_A) g_bprojh[(i - N_A) * EDGE_DIM + d] = __float2half_rn(acc);
    } else if (blk < 832) {
        int eid = (blk - 704) * 256 + tid;  // [0, 32768)
        int d = eid >> 8;
        int k = eid & 255;
        g_Wn1T[eid] = Wn1[k * NODE_DIM + d];
    } else {
        int eid = (blk - 832) * 256 + tid;  // [0, 16384)
        int d = eid >> 7;
        int k = eid & 127;
        g_Wn2T[eid] = Wn2[k * NODE_DIM + d];
    }
}

// ---------------------------------------------------------------------------
// Fused edge pipeline (R7-proven mainloop), single-pass fp16, 2 CTAs/SM.
// 8 warps (4x2): warp tile 32 x 64. One 128x128 edge tile per CTA.
// Accumulates suma partials via one 128-float atomicAdd per CTA.
// ---------------------------------------------------------------------------
__global__ void __launch_bounds__(256, 2) fused_kernel(const float* __restrict__ edge,
                                                       const float* __restrict__ be2,
                                                       float* __restrict__ out) {
    extern __shared__ __align__(128) char smem_c[];
    const uint32_t sb = smem_u32(smem_c);
    const int tid = threadIdx.x;
    const int wid = tid >> 5;
    const int lane = tid & 31;
    const int wm = wid >> 1;
    const int wn = wid & 1;
    const int m0 = blockIdx.x * 128;
    const int a_idx = m0 >> 9;
    const int b0 = m0 & (N_B - 1);

    const uint32_t a_loff = (uint32_t)(wm * 32 + (lane & 15)) * RSTRIDE + ((lane >> 4) << 4);
    const uint32_t b_loff = (uint32_t)(wn * 64 + (lane & 7) + ((lane >> 4) << 3)) * RSTRIDE +
                            (((lane >> 3) & 1) << 4);

    // ---- Prologue: B chunk0 via cp.async; A chunk0 via LDG ----
    {
        const char* src = (const char*)g_Bimg1;
#pragma unroll
        for (int i = 0; i < 4; i++) {
            int idx = tid + i * 256;
            int n = idx >> 3;
            int p = idx & 7;
            CP_ASYNC16(sb + BS_OFF + n * RSTRIDE + p * 16, src + (size_t)idx * 16);
        }
        CP_COMMIT();
    }
    float4 regsA[8];
    {
        const float* Ag = edge + (size_t)m0 * 256;
#pragma unroll
        for (int i = 0; i < 8; i++) {
            int idx = tid + i * 256;
            regsA[i] = *(const float4*)(Ag + (size_t)(idx >> 4) * 256 + (idx & 15) * 4);
        }
    }

    float acc[2][8][4];
#pragma unroll
    for (int mt = 0; mt < 2; mt++)
#pragma unroll
        for (int nt = 0; nt < 8; nt++)
#pragma unroll
            for (int q = 0; q < 4; q++) acc[mt][nt][q] = 0.f;

    // ================= GEMM1: edge_tile @ We (K=256, 4 chunks) ==============
    for (int kc = 0; kc < 4; kc++) {
        const int buf = kc & 1;
        // convert + store A chunk kc (fp32 -> fp16)
#pragma unroll
        for (int i = 0; i < 8; i++) {
            int idx = tid + i * 256;
            int row = idx >> 4;
            int f4 = idx & 15;
            float4 v = regsA[i];
            __half2 h01 = __floats2half2_rn(v.x, v.y);
            __half2 h23 = __floats2half2_rn(v.z, v.w);
            *(uint2*)(smem_c + AS_OFF + buf * BLK + (uint32_t)row * RSTRIDE + f4 * 8) =
                make_uint2(*reinterpret_cast<uint32_t*>(&h01),
                           *reinterpret_cast<uint32_t*>(&h23));
        }
        CP_WAIT_ALL();     // B chunk kc landed
        __syncthreads();
        if (kc < 3) {
            // prefetch B chunk kc+1; LDG A chunk kc+1
            const char* srcB = (const char*)(g_Bimg1 + (size_t)(kc + 1) * 8192);
#pragma unroll
            for (int i = 0; i < 4; i++) {
                int idx = tid + i * 256;
                int n = idx >> 3;
                int p = idx & 7;
                CP_ASYNC16(sb + BS_OFF + (buf ^ 1) * BLK + n * RSTRIDE + p * 16,
                           srcB + (size_t)idx * 16);
            }
            CP_COMMIT();
            const float* Ag = edge + (size_t)m0 * 256 + (kc + 1) * 64;
#pragma unroll
            for (int i = 0; i < 8; i++) {
                int idx = tid + i * 256;
                regsA[i] = *(const float4*)(Ag + (size_t)(idx >> 4) * 256 + (idx & 15) * 4);
            }
        } else {
            // kc==3: BS buf0 (chunk2) fully consumed -> prefetch We2 chunk0
            const char* srcW = (const char*)g_Bimg2;
#pragma unroll
            for (int i = 0; i < 4; i++) {
                int idx = tid + i * 256;
                int n = idx >> 3;
                int p = idx & 7;
                CP_ASYNC16(sb + BS_OFF + 0 * BLK + n * RSTRIDE + p * 16,
                           srcW + (size_t)idx * 16);
            }
            CP_COMMIT();
        }
        // MMA over chunk kc
#pragma unroll
        for (int ks = 0; ks < 4; ks++) {
            const uint32_t kb = ks << 5;
            const uint32_t aB = sb + AS_OFF + buf * BLK + a_loff + kb;
            const uint32_t bB = sb + BS_OFF + buf * BLK + b_loff + kb;
            uint32_t af[2][4];
            ldsm_x4(aB, af[0]);
            ldsm_x4(aB + 16 * RSTRIDE, af[1]);
#pragma unroll
            for (int np = 0; np < 4; np++) {
                uint32_t bf[4];
                ldsm_x4(bB + np * 16 * RSTRIDE, bf);
#pragma unroll
                for (int mt = 0; mt < 2; mt++) {
                    mma_f16(acc[mt][2 * np], af[mt], bf[0], bf[1]);
                    mma_f16(acc[mt][2 * np + 1], af[mt], bf[2], bf[3]);
                }
            }
        }
    }
    // All GEMM1 reads of AS/BS retire before h / We2 overwrite them.
    __syncthreads();

    // We2 chunk1 -> BS buf1
    {
        const char* srcW = (const char*)(g_Bimg2 + 8192);
#pragma unroll
        for (int i = 0; i < 4; i++) {
            int idx = tid + i * 256;
            int n = idx >> 3;
            int p = idx & 7;
            CP_ASYNC16(sb + BS_OFF + 1 * BLK + n * RSTRIDE + p * 16, srcW + (size_t)idx * 16);
        }
        CP_COMMIT();
    }

    // ---- Epilogue 1: h = relu(D + aproj + bproj) -> fp16 images in AS bufs ----
    {
        const int qrow = lane >> 2;
        const int qcol = (lane & 3) * 2;
#pragma unroll
        for (int mt = 0; mt < 2; mt++) {
            int r_base = wm * 32 + mt * 16 + qrow;
#pragma unroll
            for (int nt = 0; nt < 8; nt++) {
                int col = wn * 64 + nt * 8 + qcol;
                float2 ap = __ldg((const float2*)(g_aproj + a_idx * 128 + col));
#pragma unroll
                for (int hf = 0; hf < 2; hf++) {
                    int row = r_base + 8 * hf;
                    __half2 bph = *(const __half2*)(g_bprojh + (size_t)(b0 + row) * 128 + col);
                    float2 bp = __half22float2(bph);
                    float v0 = fmaxf(acc[mt][nt][2 * hf] + ap.x + bp.x, 0.f);
                    float v1 = fmaxf(acc[mt][nt][2 * hf + 1] + ap.y + bp.y, 0.f);
                    __half2 h01 = __floats2half2_rn(v0, v1);
                    int ch = col >> 6;
                    *(uint32_t*)(smem_c + AS_OFF + ch * BLK + (uint32_t)row * RSTRIDE +
                                 (col & 63) * 2) = *reinterpret_cast<uint32_t*>(&h01);
                    acc[mt][nt][2 * hf] = 0.f;
                    acc[mt][nt][2 * hf + 1] = 0.f;
                }
            }
        }
    }
    CP_WAIT_ALL();   // We2 chunks landed
    __syncthreads();

    // ================= GEMM2: h @ We2 (K=128, 2 chunks) =====================
#pragma unroll
    for (int ch = 0; ch < 2; ch++) {
#pragma unroll
        for (int ks = 0; ks < 4; ks++) {
            const uint32_t kb = ks << 5;
            const uint32_t aB = sb + AS_OFF + ch * BLK + a_loff + kb;
            const uint32_t bB = sb + BS_OFF + ch * BLK + b_loff + kb;
            uint32_t af[2][4];
            ldsm_x4(aB, af[0]);
            ldsm_x4(aB + 16 * RSTRIDE, af[1]);
#pragma unroll
            for (int np = 0; np < 4; np++) {
                uint32_t bf[4];
                ldsm_x4(bB + np * 16 * RSTRIDE, bf);
#pragma unroll
                for (int mt = 0; mt < 2; mt++) {
                    mma_f16(acc[mt][2 * np], af[mt], bf[0], bf[1]);
                    mma_f16(acc[mt][2 * np + 1], af[mt], bf[2], bf[3]);
                }
            }
        }
    }

    // ---- Epilogue 2: out = relu(D + be2); accumulate suma partials ----
    {
        float* wsumS = (float*)(smem_c + WSUM_OFF);  // [8 warps][64]
        const int qrow = lane >> 2;
        const int qc = lane & 3;
#pragma unroll
        for (int nt = 0; nt < 8; nt++) {
            int col = wn * 64 + nt * 8 + qc * 2;
            float2 bz = __ldg((const float2*)(be2 + col));
            float p0 = 0.f, p1 = 0.f;
#pragma unroll
            for (int mt = 0; mt < 2; mt++) {
                int r_base = wm * 32 + mt * 16 + qrow;
#pragma unroll
                for (int hf = 0; hf < 2; hf++) {
                    int row = r_base + 8 * hf;
                    float2 w;
                    w.x = fmaxf(acc[mt][nt][2 * hf] + bz.x, 0.f);
                    w.y = fmaxf(acc[mt][nt][2 * hf + 1] + bz.y, 0.f);
                    *(float2*)(out + (size_t)(m0 + row) * 128 + col) = w;
                    p0 += w.x;
                    p1 += w.y;
                }
            }
            p0 += __shfl_xor_sync(0xffffffffu, p0, 4);
            p0 += __shfl_xor_sync(0xffffffffu, p0, 8);
            p0 += __shfl_xor_sync(0xffffffffu, p0, 16);
            p1 += __shfl_xor_sync(0xffffffffu, p1, 4);
            p1 += __shfl_xor_sync(0xffffffffu, p1, 8);
            p1 += __shfl_xor_sync(0xffffffffu, p1, 16);
            if (lane < 4) {
                wsumS[wid * 64 + nt * 8 + lane * 2] = p0;
                wsumS[wid * 64 + nt * 8 + lane * 2 + 1] = p1;
            }
        }
        __syncthreads();
        if (tid < 128) {
            int wn2 = tid >> 6;
            int off = tid & 63;
            float s = wsumS[(0 * 2 + wn2) * 64 + off] + wsumS[(1 * 2 + wn2) * 64 + off] +
                      wsumS[(2 * 2 + wn2) * 64 + off] + wsumS[(3 * 2 + wn2) * 64 + off];
            atomicAdd(g_suma + a_idx * 128 + tid, s);
        }
    }
}

// ---------------------------------------------------------------------------
// K4: column sums (over a) -> g_sumb, 4-way split over a + atomics.
// ---------------------------------------------------------------------------
__global__ void __launch_bounds__(256) sum_b_kernel(const float* __restrict__ lat) {
    __shared__ float4 red[8][33];
    int b = blockIdx.x & (N_B - 1);
    int as = blockIdx.x >> 9;           // a-slice [as*128, as*128+128)
    int d4 = threadIdx.x & 31;
    int g = threadIdx.x >> 5;
    float x = 0.f, y = 0.f, z = 0.f, w = 0.f;
    const float4* p = (const float4*)lat + (size_t)b * 32;
    int a_end = as * 128 + 128;
    for (int a2 = as * 128 + g; a2 < a_end; a2 += 8) {
        float4 v = p[(size_t)a2 * (N_B * 32) + d4];
        x += v.x; y += v.y; z += v.z; w += v.w;
    }
    red[g][d4] = make_float4(x, y, z, w);
    __syncthreads();
    if (g == 0) {
#pragma unroll
        for (int k = 1; k < 8; k++) {
            float4 v = red[k][d4];
            x += v.x; y += v.y; z += v.z; w += v.w;
        }
        float* dst = g_sumb + b * EDGE_DIM + d4 * 4;
        atomicAdd(dst + 0, x);
        atomicAdd(dst + 1, y);
        atomicAdd(dst + 2, z);
        atomicAdd(dst + 3, w);
    }
}

// ---------------------------------------------------------------------------
// K5: node MLPs. 256 threads/row: layer k-dim split in half across thread
// groups, transposed weights give contiguous float4 rows, 4 rotating accs.
// ---------------------------------------------------------------------------
__global__ void __launch_bounds__(256) node_mlp_kernel(const float* __restrict__ na,
                                                       const float* __restrict__ nb,
                                                       const float* __restrict__ bn1,
                                                       const float* __restrict__ bn2,
                                                       float* __restrict__ out_nodes) {
    __shared__ float x[2 * NODE_DIM];
    __shared__ float part[256];
    __shared__ float hsm[NODE_DIM];
    int i = blockIdx.x;
    int tid = threadIdx.x;
    int d = tid & 127;
    int half = tid >> 7;
    const float* emb;
    const float* sum;
    float* o;
    if (i < N_A) {
        emb = na + i * NODE_DIM;
        sum = g_suma + i * EDGE_DIM;
        o = out_nodes + (size_t)i * NODE_DIM;
    } else {
        emb = nb + (i - N_A) * NODE_DIM;
        sum = g_sumb + (i - N_A) * EDGE_DIM;
        o = out_nodes + (size_t)N_A * NODE_DIM + (size_t)(i - N_A) * NODE_DIM;
    }
    if (half == 0) x[d] = emb[d];
    else x[NODE_DIM + d] = sum[d];
    __syncthreads();

    // Layer 1: thread (d, half) covers k in [half*128, half*128+128)
    {
        const float4* Wr = (const float4*)(g_Wn1T + d * 256 + half * 128);
        const float4* xv = (const float4*)(x + half * 128);
        float a0 = 0.f, a1 = 0.f, a2 = 0.f, a3 = 0.f;
#pragma unroll
        for (int k4 = 0; k4 < 32; k4 += 4) {
            float4 w0 = Wr[k4 + 0], v0 = xv[k4 + 0];
            float4 w1 = Wr[k4 + 1], v1 = xv[k4 + 1];
            float4 w2 = Wr[k4 + 2], v2 = xv[k4 + 2];
            float4 w3 = Wr[k4 + 3], v3 = xv[k4 + 3];
            a0 = fmaf(w0.x, v0.x, fmaf(w0.y, v0.y, fmaf(w0.z, v0.z, fmaf(w0.w, v0.w, a0))));
            a1 = fmaf(w1.x, v1.x, fmaf(w1.y, v1.y, fmaf(w1.z, v1.z, fmaf(w1.w, v1.w, a1))));
            a2 = fmaf(w2.x, v2.x, fmaf(w2.y, v2.y, fmaf(w2.z, v2.z, fmaf(w2.w, v2.w, a2))));
            a3 = fmaf(w3.x, v3.x, fmaf(w3.y, v3.y, fmaf(w3.z, v3.z, fmaf(w3.w, v3.w, a3))));
        }
        part[tid] = (a0 + a1) + (a2 + a3);
    }
    __syncthreads();
    if (half == 0) hsm[d] = fmaxf(part[d] + part[d + 128] + bn1[d], 0.f);
    __syncthreads();

    // Layer 2: thread (d, half) covers k in [half*64, half*64+64)
    {
        const float4* Wr = (const float4*)(g_Wn2T + d * 128 + half * 64);
        const float4* xv = (const float4*)(hsm + half * 64);
        float a0 = 0.f, a1 = 0.f, a2 = 0.f, a3 = 0.f;
#pragma unroll
        for (int k4 = 0; k4 < 16; k4 += 4) {
            float4 w0 = Wr[k4 + 0], v0 = xv[k4 + 0];
            float4 w1 = Wr[k4 + 1], v1 = xv[k4 + 1];
            float4 w2 = Wr[k4 + 2], v2 = xv[k4 + 2];
            float4 w3 = Wr[k4 + 3], v3 = xv[k4 + 3];
            a0 = fmaf(w0.x, v0.x, fmaf(w0.y, v0.y, fmaf(w0.z, v0.z, fmaf(w0.w, v0.w, a0))));
            a1 = fmaf(w1.x, v1.x, fmaf(w1.y, v1.y, fmaf(w1.z, v1.z, fmaf(w1.w, v1.w, a1))));
            a2 = fmaf(w2.x, v2.x, fmaf(w2.y, v2.y, fmaf(w2.z, v2.z, fmaf(w2.w, v2.w, a2))));
            a3 = fmaf(w3.x, v3.x, fmaf(w3.y, v3.y, fmaf(w3.z, v3.z, fmaf(w3.w, v3.w, a3))));
        }
        part[tid] = (a0 + a1) + (a2 + a3);
    }
    __syncthreads();
    if (half == 0) o[d] = fmaxf(part[d] + part[d + 128] + bn2[d], 0.f);
}

// ---------------------------------------------------------------------------
extern "C" void kernel_launch(void* const* d_in, const int* in_sizes, int n_in,
                              void* d_out, int out_size) {
    const float* edge = (const float*)d_in[0];
    const float* na   = (const float*)d_in[1];
    const float* nb   = (const float*)d_in[2];
    const float* We1  = (const float*)d_in[3];
    const float* be1  = (const float*)d_in[4];
    const float* We2  = (const float*)d_in[5];
    const float* be2  = (const float*)d_in[6];
    const float* Wn1  = (const float*)d_in[7];
    const float* bn1  = (const float*)d_in[8];
    const float* Wn2  = (const float*)d_in[9];
    const float* bn2  = (const float*)d_in[10];
    float* out = (float*)d_out;

    static int smem_set = 0;
    if (!smem_set) {
        cudaFuncSetAttribute(fused_kernel, cudaFuncAttributeMaxDynamicSharedMemorySize,
                             SMEM_BYTES);
        smem_set = 1;
    }

    init_kernel<<<896, 256>>>(We1, We2, na, nb, be1, Wn1, Wn2);
    fused_kernel<<<M_EDGES / 128, 256, SMEM_BYTES>>>(edge, be2, out);
    sum_b_kernel<<<4 * N_B, 256>>>(out);
    node_mlp_kernel<<<N_A + N_B, 256>>>(na, nb, bn1, bn2,
                                        out + (size_t)M_EDGES * EDGE_DIM);
}

// round 10
// speedup vs baseline: 1.1670x; 1.1670x over previous
#include <cuda_runtime.h>
#include <cuda_fp16.h>
#include <cstdint>
#include <cstddef>

#define NODE_DIM 128
#define EDGE_DIM 128
#define N_A 512
#define N_B 512
#define M_EDGES (N_A * N_B)

// ---------------------------------------------------------------------------
// Device scratch
// ---------------------------------------------------------------------------
__device__ float g_aproj[N_A * EDGE_DIM];     // nodes_a @ Wa + be1
__device__ float g_bproj[N_B * EDGE_DIM];     // nodes_b @ Wb (fp32)
__device__ __half g_bprojh[N_B * EDGE_DIM];   // fp16 copy for fused epilogue
__device__ float g_suma[N_A * EDGE_DIM];      // accumulated by fused kernel
__device__ float g_sumb[N_B * EDGE_DIM];      // accumulated by sum_b kernel
// Pre-transposed fp16 weight images: [chunk][n(128)][k(64)]
__device__ __half g_Bimg1[4 * 8192];  // We  (256x128): 4 K-chunks
__device__ __half g_Bimg2[2 * 8192];  // We2 (128x128): 2 K-chunks

// ---------------------------------------------------------------------------
// PTX helpers (compute_80+ only)
// ---------------------------------------------------------------------------
__device__ __forceinline__ uint32_t smem_u32(const void* p) {
    uint32_t a;
    asm("{ .reg .u64 t; cvta.to.shared.u64 t, %1; cvt.u32.u64 %0, t; }" : "=r"(a) : "l"(p));
    return a;
}
__device__ __forceinline__ void ldsm_x4(uint32_t addr, uint32_t* r) {
    asm volatile("ldmatrix.sync.aligned.m8n8.x4.shared.b16 {%0,%1,%2,%3}, [%4];"
                 : "=r"(r[0]), "=r"(r[1]), "=r"(r[2]), "=r"(r[3]) : "r"(addr));
}
__device__ __forceinline__ void mma_f16(float* c, const uint32_t* a, uint32_t b0, uint32_t b1) {
    asm volatile(
        "mma.sync.aligned.m16n8k16.row.col.f32.f16.f16.f32 "
        "{%0,%1,%2,%3}, {%4,%5,%6,%7}, {%8,%9}, {%0,%1,%2,%3};"
        : "+f"(c[0]), "+f"(c[1]), "+f"(c[2]), "+f"(c[3])
        : "r"(a[0]), "r"(a[1]), "r"(a[2]), "r"(a[3]), "r"(b0), "r"(b1));
}
#define CP_ASYNC16(dst, src) \
    asm volatile("cp.async.cg.shared.global [%0], [%1], 16;" :: "r"(dst), "l"(src))
#define CP_COMMIT() asm volatile("cp.async.commit_group;" ::: "memory")
#define CP_WAIT_ALL() asm volatile("cp.async.wait_group 0;" ::: "memory")

// SMEM layout. Padded row stride: 72 fp16 = 144 B (conflict-free ldmatrix).
#define RSTRIDE 144
#define BLK 18432                   /* one [128][72] b16 image */
#define AS_OFF 0                    /* A bufs 0,1 -> later h chunks 0,1   */
#define BS_OFF (2 * BLK)            /* B bufs 0,1 -> later We2 chunks 0,1 */
#define WSUM_OFF (4 * BLK)          /* 8 warps x 64 floats = 2 KB         */
#define SMEM_BYTES (4 * BLK + 2048) /* 75776 -> 2 CTAs/SM                 */

// ---------------------------------------------------------------------------
// init: [0,128) Bimg1; [128,192) Bimg2; [192,704) projections + zero sums.
// ---------------------------------------------------------------------------
__global__ void __launch_bounds__(256) init_kernel(const float* __restrict__ We1,
                                                   const float* __restrict__ We2,
                                                   const float* __restrict__ na,
                                                   const float* __restrict__ nb,
                                                   const float* __restrict__ be1) {
    int blk = blockIdx.x;
    int tid = threadIdx.x;
    if (blk < 128) {
        int eid = blk * 256 + tid;          // [0, 32768)
        int kc = eid >> 13;
        int n = (eid >> 6) & 127;
        int kk = eid & 63;
        float wv = We1[(2 * NODE_DIM + kc * 64 + kk) * EDGE_DIM + n];
        g_Bimg1[(size_t)kc * 8192 + n * 64 + kk] = __float2half_rn(wv);
    } else if (blk < 192) {
        int eid = (blk - 128) * 256 + tid;  // [0, 16384)
        int kc = eid >> 13;
        int n = (eid >> 6) & 127;
        int kk = eid & 63;
        float wv = We2[(kc * 64 + kk) * EDGE_DIM + n];
        g_Bimg2[(size_t)kc * 8192 + n * 64 + kk] = __float2half_rn(wv);
    } else {
        __shared__ float x[2][NODE_DIM];
        int sub = tid >> 7;                 // 0/1: node within block
        int i = (blk - 192) * 2 + sub;      // [0, 1024)
        int d = tid & 127;
        const float* src;
        const float* W;
        float* dst;
        float acc;
        if (i < N_A) {
            src = na + i * NODE_DIM;
            dst = g_aproj + i * EDGE_DIM;
            W = We1;
            acc = be1[d];
            g_suma[i * EDGE_DIM + d] = 0.f;
        } else {
            int j = i - N_A;
            src = nb + j * NODE_DIM;
            dst = g_bproj + j * EDGE_DIM;
            W = We1 + NODE_DIM * EDGE_DIM;
            acc = 0.f;
            g_sumb[j * EDGE_DIM + d] = 0.f;
        }
        x[sub][d] = src[d];
        __syncthreads();
#pragma unroll 8
        for (int k = 0; k < NODE_DIM; k++) acc = fmaf(x[sub][k], W[k * EDGE_DIM + d], acc);
        dst[d] = acc;
        if (i >= N_A) g_bprojh[(i - N_A) * EDGE_DIM + d] = __float2half_rn(acc);
    }
}

// ---------------------------------------------------------------------------
// Fused edge pipeline (R7-proven mainloop), single-pass fp16, 2 CTAs/SM.
// 8 warps (4x2): warp tile 32 x 64. One 128x128 edge tile per CTA.
// Accumulates suma partials via one 128-float atomicAdd per CTA.
// ---------------------------------------------------------------------------
__global__ void __launch_bounds__(256, 2) fused_kernel(const float* __restrict__ edge,
                                                       const float* __restrict__ be2,
                                                       float* __restrict__ out) {
    extern __shared__ __align__(128) char smem_c[];
    const uint32_t sb = smem_u32(smem_c);
    const int tid = threadIdx.x;
    const int wid = tid >> 5;
    const int lane = tid & 31;
    const int wm = wid >> 1;
    const int wn = wid & 1;
    const int m0 = blockIdx.x * 128;
    const int a_idx = m0 >> 9;
    const int b0 = m0 & (N_B - 1);

    const uint32_t a_loff = (uint32_t)(wm * 32 + (lane & 15)) * RSTRIDE + ((lane >> 4) << 4);
    const uint32_t b_loff = (uint32_t)(wn * 64 + (lane & 7) + ((lane >> 4) << 3)) * RSTRIDE +
                            (((lane >> 3) & 1) << 4);

    // ---- Prologue: B chunk0 via cp.async; A chunk0 via LDG ----
    {
        const char* src = (const char*)g_Bimg1;
#pragma unroll
        for (int i = 0; i < 4; i++) {
            int idx = tid + i * 256;
            int n = idx >> 3;
            int p = idx & 7;
            CP_ASYNC16(sb + BS_OFF + n * RSTRIDE + p * 16, src + (size_t)idx * 16);
        }
        CP_COMMIT();
    }
    float4 regsA[8];
    {
        const float* Ag = edge + (size_t)m0 * 256;
#pragma unroll
        for (int i = 0; i < 8; i++) {
            int idx = tid + i * 256;
            regsA[i] = *(const float4*)(Ag + (size_t)(idx >> 4) * 256 + (idx & 15) * 4);
        }
    }

    float acc[2][8][4];
#pragma unroll
    for (int mt = 0; mt < 2; mt++)
#pragma unroll
        for (int nt = 0; nt < 8; nt++)
#pragma unroll
            for (int q = 0; q < 4; q++) acc[mt][nt][q] = 0.f;

    // ================= GEMM1: edge_tile @ We (K=256, 4 chunks) ==============
    for (int kc = 0; kc < 4; kc++) {
        const int buf = kc & 1;
        // convert + store A chunk kc (fp32 -> fp16)
#pragma unroll
        for (int i = 0; i < 8; i++) {
            int idx = tid + i * 256;
            int row = idx >> 4;
            int f4 = idx & 15;
            float4 v = regsA[i];
            __half2 h01 = __floats2half2_rn(v.x, v.y);
            __half2 h23 = __floats2half2_rn(v.z, v.w);
            *(uint2*)(smem_c + AS_OFF + buf * BLK + (uint32_t)row * RSTRIDE + f4 * 8) =
                make_uint2(*reinterpret_cast<uint32_t*>(&h01),
                           *reinterpret_cast<uint32_t*>(&h23));
        }
        CP_WAIT_ALL();     // B chunk kc landed
        __syncthreads();
        if (kc < 3) {
            // prefetch B chunk kc+1; LDG A chunk kc+1
            const char* srcB = (const char*)(g_Bimg1 + (size_t)(kc + 1) * 8192);
#pragma unroll
            for (int i = 0; i < 4; i++) {
                int idx = tid + i * 256;
                int n = idx >> 3;
                int p = idx & 7;
                CP_ASYNC16(sb + BS_OFF + (buf ^ 1) * BLK + n * RSTRIDE + p * 16,
                           srcB + (size_t)idx * 16);
            }
            CP_COMMIT();
            const float* Ag = edge + (size_t)m0 * 256 + (kc + 1) * 64;
#pragma unroll
            for (int i = 0; i < 8; i++) {
                int idx = tid + i * 256;
                regsA[i] = *(const float4*)(Ag + (size_t)(idx >> 4) * 256 + (idx & 15) * 4);
            }
        } else {
            // kc==3: BS buf0 (chunk2) fully consumed -> prefetch We2 chunk0
            const char* srcW = (const char*)g_Bimg2;
#pragma unroll
            for (int i = 0; i < 4; i++) {
                int idx = tid + i * 256;
                int n = idx >> 3;
                int p = idx & 7;
                CP_ASYNC16(sb + BS_OFF + 0 * BLK + n * RSTRIDE + p * 16,
                           srcW + (size_t)idx * 16);
            }
            CP_COMMIT();
        }
        // MMA over chunk kc
#pragma unroll
        for (int ks = 0; ks < 4; ks++) {
            const uint32_t kb = ks << 5;
            const uint32_t aB = sb + AS_OFF + buf * BLK + a_loff + kb;
            const uint32_t bB = sb + BS_OFF + buf * BLK + b_loff + kb;
            uint32_t af[2][4];
            ldsm_x4(aB, af[0]);
            ldsm_x4(aB + 16 * RSTRIDE, af[1]);
#pragma unroll
            for (int np = 0; np < 4; np++) {
                uint32_t bf[4];
                ldsm_x4(bB + np * 16 * RSTRIDE, bf);
#pragma unroll
                for (int mt = 0; mt < 2; mt++) {
                    mma_f16(acc[mt][2 * np], af[mt], bf[0], bf[1]);
                    mma_f16(acc[mt][2 * np + 1], af[mt], bf[2], bf[3]);
                }
            }
        }
    }
    // All GEMM1 reads of AS/BS retire before h / We2 overwrite them.
    __syncthreads();

    // We2 chunk1 -> BS buf1
    {
        const char* srcW = (const char*)(g_Bimg2 + 8192);
#pragma unroll
        for (int i = 0; i < 4; i++) {
            int idx = tid + i * 256;
            int n = idx >> 3;
            int p = idx & 7;
            CP_ASYNC16(sb + BS_OFF + 1 * BLK + n * RSTRIDE + p * 16, srcW + (size_t)idx * 16);
        }
        CP_COMMIT();
    }

    // ---- Epilogue 1: h = relu(D + aproj + bproj) -> fp16 images in AS bufs ----
    {
        const int qrow = lane >> 2;
        const int qcol = (lane & 3) * 2;
#pragma unroll
        for (int mt = 0; mt < 2; mt++) {
            int r_base = wm * 32 + mt * 16 + qrow;
#pragma unroll
            for (int nt = 0; nt < 8; nt++) {
                int col = wn * 64 + nt * 8 + qcol;
                float2 ap = __ldg((const float2*)(g_aproj + a_idx * 128 + col));
#pragma unroll
                for (int hf = 0; hf < 2; hf++) {
                    int row = r_base + 8 * hf;
                    __half2 bph = *(const __half2*)(g_bprojh + (size_t)(b0 + row) * 128 + col);
                    float2 bp = __half22float2(bph);
                    float v0 = fmaxf(acc[mt][nt][2 * hf] + ap.x + bp.x, 0.f);
                    float v1 = fmaxf(acc[mt][nt][2 * hf + 1] + ap.y + bp.y, 0.f);
                    __half2 h01 = __floats2half2_rn(v0, v1);
                    int ch = col >> 6;
                    *(uint32_t*)(smem_c + AS_OFF + ch * BLK + (uint32_t)row * RSTRIDE +
                                 (col & 63) * 2) = *reinterpret_cast<uint32_t*>(&h01);
                    acc[mt][nt][2 * hf] = 0.f;
                    acc[mt][nt][2 * hf + 1] = 0.f;
                }
            }
        }
    }
    CP_WAIT_ALL();   // We2 chunks landed
    __syncthreads();

    // ================= GEMM2: h @ We2 (K=128, 2 chunks) =====================
#pragma unroll
    for (int ch = 0; ch < 2; ch++) {
#pragma unroll
        for (int ks = 0; ks < 4; ks++) {
            const uint32_t kb = ks << 5;
            const uint32_t aB = sb + AS_OFF + ch * BLK + a_loff + kb;
            const uint32_t bB = sb + BS_OFF + ch * BLK + b_loff + kb;
            uint32_t af[2][4];
            ldsm_x4(aB, af[0]);
            ldsm_x4(aB + 16 * RSTRIDE, af[1]);
#pragma unroll
            for (int np = 0; np < 4; np++) {
                uint32_t bf[4];
                ldsm_x4(bB + np * 16 * RSTRIDE, bf);
#pragma unroll
                for (int mt = 0; mt < 2; mt++) {
                    mma_f16(acc[mt][2 * np], af[mt], bf[0], bf[1]);
                    mma_f16(acc[mt][2 * np + 1], af[mt], bf[2], bf[3]);
                }
            }
        }
    }

    // ---- Epilogue 2: out = relu(D + be2); accumulate suma partials ----
    {
        float* wsumS = (float*)(smem_c + WSUM_OFF);  // [8 warps][64]
        const int qrow = lane >> 2;
        const int qc = lane & 3;
#pragma unroll
        for (int nt = 0; nt < 8; nt++) {
            int col = wn * 64 + nt * 8 + qc * 2;
            float2 bz = __ldg((const float2*)(be2 + col));
            float p0 = 0.f, p1 = 0.f;
#pragma unroll
            for (int mt = 0; mt < 2; mt++) {
                int r_base = wm * 32 + mt * 16 + qrow;
#pragma unroll
                for (int hf = 0; hf < 2; hf++) {
                    int row = r_base + 8 * hf;
                    float2 w;
                    w.x = fmaxf(acc[mt][nt][2 * hf] + bz.x, 0.f);
                    w.y = fmaxf(acc[mt][nt][2 * hf + 1] + bz.y, 0.f);
                    *(float2*)(out + (size_t)(m0 + row) * 128 + col) = w;
                    p0 += w.x;
                    p1 += w.y;
                }
            }
            p0 += __shfl_xor_sync(0xffffffffu, p0, 4);
            p0 += __shfl_xor_sync(0xffffffffu, p0, 8);
            p0 += __shfl_xor_sync(0xffffffffu, p0, 16);
            p1 += __shfl_xor_sync(0xffffffffu, p1, 4);
            p1 += __shfl_xor_sync(0xffffffffu, p1, 8);
            p1 += __shfl_xor_sync(0xffffffffu, p1, 16);
            if (lane < 4) {
                wsumS[wid * 64 + nt * 8 + lane * 2] = p0;
                wsumS[wid * 64 + nt * 8 + lane * 2 + 1] = p1;
            }
        }
        __syncthreads();
        if (tid < 128) {
            int wn2 = tid >> 6;
            int off = tid & 63;
            float s = wsumS[(0 * 2 + wn2) * 64 + off] + wsumS[(1 * 2 + wn2) * 64 + off] +
                      wsumS[(2 * 2 + wn2) * 64 + off] + wsumS[(3 * 2 + wn2) * 64 + off];
            atomicAdd(g_suma + a_idx * 128 + tid, s);
        }
    }
}

// ---------------------------------------------------------------------------
// K4: column sums (over a) -> g_sumb, 4-way split over a + atomics.
// ---------------------------------------------------------------------------
__global__ void __launch_bounds__(256) sum_b_kernel(const float* __restrict__ lat) {
    __shared__ float4 red[8][33];
    int b = blockIdx.x & (N_B - 1);
    int as = blockIdx.x >> 9;           // a-slice [as*128, as*128+128)
    int d4 = threadIdx.x & 31;
    int g = threadIdx.x >> 5;
    float x = 0.f, y = 0.f, z = 0.f, w = 0.f;
    const float4* p = (const float4*)lat + (size_t)b * 32;
    int a_end = as * 128 + 128;
    for (int a2 = as * 128 + g; a2 < a_end; a2 += 8) {
        float4 v = p[(size_t)a2 * (N_B * 32) + d4];
        x += v.x; y += v.y; z += v.z; w += v.w;
    }
    red[g][d4] = make_float4(x, y, z, w);
    __syncthreads();
    if (g == 0) {
#pragma unroll
        for (int k = 1; k < 8; k++) {
            float4 v = red[k][d4];
            x += v.x; y += v.y; z += v.z; w += v.w;
        }
        float* dst = g_sumb + b * EDGE_DIM + d4 * 4;
        atomicAdd(dst + 0, x);
        atomicAdd(dst + 1, y);
        atomicAdd(dst + 2, z);
        atomicAdd(dst + 3, w);
    }
}

// ---------------------------------------------------------------------------
// K5: node MLPs, 8 nodes per block (grid 128). Thread (d, g) computes output
// dim d for 4 nodes of group g. Weight loads warp-coalesced + L1-shared
// across nodes; x reads are SMEM broadcasts.
// ---------------------------------------------------------------------------
__global__ void __launch_bounds__(256) node_mlp_kernel(const float* __restrict__ na,
                                                       const float* __restrict__ nb,
                                                       const float* __restrict__ Wn1,
                                                       const float* __restrict__ bn1,
                                                       const float* __restrict__ Wn2,
                                                       const float* __restrict__ bn2,
                                                       float* __restrict__ out_nodes) {
    __shared__ float x[8][256];
    __shared__ float h[8][128];
    const int tid = threadIdx.x;
    const int d = tid & 127;
    const int g = tid >> 7;
    const int i0 = blockIdx.x * 8;

    // load x = [emb | sum] for 8 nodes (8 floats per thread)
    for (int l = tid; l < 8 * 256; l += 256) {
        int j = l >> 8;
        int c = l & 255;
        int i = i0 + j;
        float v;
        if (i < N_A)
            v = (c < 128) ? na[i * 128 + c] : g_suma[i * 128 + (c - 128)];
        else {
            int ib = i - N_A;
            v = (c < 128) ? nb[ib * 128 + c] : g_sumb[ib * 128 + (c - 128)];
        }
        x[j][c] = v;
    }
    __syncthreads();

    // Layer 1: k = 256
    {
        float a0 = 0.f, a1 = 0.f, a2 = 0.f, a3 = 0.f;
#pragma unroll 8
        for (int k4 = 0; k4 < 64; k4++) {
            const float* wp = Wn1 + (k4 * 4) * 128 + d;
            float w0 = wp[0], w1 = wp[128], w2 = wp[256], w3 = wp[384];
            float4 x0 = *(const float4*)&x[g * 4 + 0][k4 * 4];
            float4 x1 = *(const float4*)&x[g * 4 + 1][k4 * 4];
            float4 x2 = *(const float4*)&x[g * 4 + 2][k4 * 4];
            float4 x3 = *(const float4*)&x[g * 4 + 3][k4 * 4];
            a0 = fmaf(x0.x, w0, fmaf(x0.y, w1, fmaf(x0.z, w2, fmaf(x0.w, w3, a0))));
            a1 = fmaf(x1.x, w0, fmaf(x1.y, w1, fmaf(x1.z, w2, fmaf(x1.w, w3, a1))));
            a2 = fmaf(x2.x, w0, fmaf(x2.y, w1, fmaf(x2.z, w2, fmaf(x2.w, w3, a2))));
            a3 = fmaf(x3.x, w0, fmaf(x3.y, w1, fmaf(x3.z, w2, fmaf(x3.w, w3, a3))));
        }
        float b1 = bn1[d];
        h[g * 4 + 0][d] = fmaxf(a0 + b1, 0.f);
        h[g * 4 + 1][d] = fmaxf(a1 + b1, 0.f);
        h[g * 4 + 2][d] = fmaxf(a2 + b1, 0.f);
        h[g * 4 + 3][d] = fmaxf(a3 + b1, 0.f);
    }
    __syncthreads();

    // Layer 2: k = 128
    {
        float a0 = 0.f, a1 = 0.f, a2 = 0.f, a3 = 0.f;
#pragma unroll 8
        for (int k4 = 0; k4 < 32; k4++) {
            const float* wp = Wn2 + (k4 * 4) * 128 + d;
            float w0 = wp[0], w1 = wp[128], w2 = wp[256], w3 = wp[384];
            float4 x0 = *(const float4*)&h[g * 4 + 0][k4 * 4];
            float4 x1 = *(const float4*)&h[g * 4 + 1][k4 * 4];
            float4 x2 = *(const float4*)&h[g * 4 + 2][k4 * 4];
            float4 x3 = *(const float4*)&h[g * 4 + 3][k4 * 4];
            a0 = fmaf(x0.x, w0, fmaf(x0.y, w1, fmaf(x0.z, w2, fmaf(x0.w, w3, a0))));
            a1 = fmaf(x1.x, w0, fmaf(x1.y, w1, fmaf(x1.z, w2, fmaf(x1.w, w3, a1))));
            a2 = fmaf(x2.x, w0, fmaf(x2.y, w1, fmaf(x2.z, w2, fmaf(x2.w, w3, a2))));
            a3 = fmaf(x3.x, w0, fmaf(x3.y, w1, fmaf(x3.z, w2, fmaf(x3.w, w3, a3))));
        }
        float b2 = bn2[d];
        // out layout: nodes_a rows then nodes_b rows are contiguous -> i*128+d
        out_nodes[(size_t)(i0 + g * 4 + 0) * 128 + d] = fmaxf(a0 + b2, 0.f);
        out_nodes[(size_t)(i0 + g * 4 + 1) * 128 + d] = fmaxf(a1 + b2, 0.f);
        out_nodes[(size_t)(i0 + g * 4 + 2) * 128 + d] = fmaxf(a2 + b2, 0.f);
        out_nodes[(size_t)(i0 + g * 4 + 3) * 128 + d] = fmaxf(a3 + b2, 0.f);
    }
}

// ---------------------------------------------------------------------------
extern "C" void kernel_launch(void* const* d_in, const int* in_sizes, int n_in,
                              void* d_out, int out_size) {
    const float* edge = (const float*)d_in[0];
    const float* na   = (const float*)d_in[1];
    const float* nb   = (const float*)d_in[2];
    const float* We1  = (const float*)d_in[3];
    const float* be1  = (const float*)d_in[4];
    const float* We2  = (const float*)d_in[5];
    const float* be2  = (const float*)d_in[6];
    const float* Wn1  = (const float*)d_in[7];
    const float* bn1  = (const float*)d_in[8];
    const float* Wn2  = (const float*)d_in[9];
    const float* bn2  = (const float*)d_in[10];
    float* out = (float*)d_out;

    static int smem_set = 0;
    if (!smem_set) {
        cudaFuncSetAttribute(fused_kernel, cudaFuncAttributeMaxDynamicSharedMemorySize,
                             SMEM_BYTES);
        smem_set = 1;
    }

    init_kernel<<<704, 256>>>(We1, We2, na, nb, be1);
    fused_kernel<<<M_EDGES / 128, 256, SMEM_BYTES>>>(edge, be2, out);
    sum_b_kernel<<<4 * N_B, 256>>>(out);
    node_mlp_kernel<<<128, 256>>>(na, nb, Wn1, bn1, Wn2, bn2,
                                  out + (size_t)M_EDGES * EDGE_DIM);
}

// round 11
// speedup vs baseline: 1.3200x; 1.1311x over previous
#include <cuda_runtime.h>
#include <cuda_fp16.h>
#include <cstdint>
#include <cstddef>

#define NODE_DIM 128
#define EDGE_DIM 128
#define N_A 512
#define N_B 512
#define M_EDGES (N_A * N_B)

// ---------------------------------------------------------------------------
// Device scratch
// ---------------------------------------------------------------------------
__device__ float g_aproj[N_A * EDGE_DIM];     // nodes_a @ Wa + be1
__device__ float g_bproj[N_B * EDGE_DIM];     // nodes_b @ Wb (fp32)
__device__ __half g_bprojh[N_B * EDGE_DIM];   // fp16 copy for fused epilogue
__device__ float g_suma[N_A * EDGE_DIM];      // accumulated by fused kernel
__device__ float g_sumb[N_B * EDGE_DIM];      // accumulated by sum_b kernel
// Pre-transposed fp16 weight images: [chunk][n(128)][k(64)]
__device__ __half g_Bimg1[4 * 8192];   // We  (256x128): 4 K-chunks
__device__ __half g_Bimg2[2 * 8192];   // We2 (128x128): 2 K-chunks
__device__ __half g_Wn1img[4 * 8192];  // Wn1 (256x128): 4 K-chunks
__device__ __half g_Wn2img[2 * 8192];  // Wn2 (128x128): 2 K-chunks

// ---------------------------------------------------------------------------
// PTX helpers (compute_80+ only)
// ---------------------------------------------------------------------------
__device__ __forceinline__ uint32_t smem_u32(const void* p) {
    uint32_t a;
    asm("{ .reg .u64 t; cvta.to.shared.u64 t, %1; cvt.u32.u64 %0, t; }" : "=r"(a) : "l"(p));
    return a;
}
__device__ __forceinline__ void ldsm_x4(uint32_t addr, uint32_t* r) {
    asm volatile("ldmatrix.sync.aligned.m8n8.x4.shared.b16 {%0,%1,%2,%3}, [%4];"
                 : "=r"(r[0]), "=r"(r[1]), "=r"(r[2]), "=r"(r[3]) : "r"(addr));
}
__device__ __forceinline__ void mma_f16(float* c, const uint32_t* a, uint32_t b0, uint32_t b1) {
    asm volatile(
        "mma.sync.aligned.m16n8k16.row.col.f32.f16.f16.f32 "
        "{%0,%1,%2,%3}, {%4,%5,%6,%7}, {%8,%9}, {%0,%1,%2,%3};"
        : "+f"(c[0]), "+f"(c[1]), "+f"(c[2]), "+f"(c[3])
        : "r"(a[0]), "r"(a[1]), "r"(a[2]), "r"(a[3]), "r"(b0), "r"(b1));
}
#define CP_ASYNC16(dst, src) \
    asm volatile("cp.async.cg.shared.global [%0], [%1], 16;" :: "r"(dst), "l"(src))
#define CP_COMMIT() asm volatile("cp.async.commit_group;" ::: "memory")
#define CP_WAIT_ALL() asm volatile("cp.async.wait_group 0;" ::: "memory")

// SMEM layout. Padded row stride: 72 fp16 = 144 B (conflict-free ldmatrix).
#define RSTRIDE 144
#define BLK 18432                   /* one [128][72] b16 image */
#define AS_OFF 0                    /* A bufs 0,1 -> later h chunks 0,1   */
#define BS_OFF (2 * BLK)            /* B bufs 0,1 -> later We2 chunks 0,1 */
#define WSUM_OFF (4 * BLK)          /* 8 warps x 64 floats = 2 KB         */
#define SMEM_BYTES (4 * BLK + 2048) /* 75776 -> 2 CTAs/SM                 */

// ---------------------------------------------------------------------------
// init: [0,128) Bimg1; [128,192) Bimg2; [192,704) projections + zero sums;
//       [704,832) Wn1img; [832,896) Wn2img.
// ---------------------------------------------------------------------------
__global__ void __launch_bounds__(256) init_kernel(const float* __restrict__ We1,
                                                   const float* __restrict__ We2,
                                                   const float* __restrict__ na,
                                                   const float* __restrict__ nb,
                                                   const float* __restrict__ be1,
                                                   const float* __restrict__ Wn1,
                                                   const float* __restrict__ Wn2) {
    int blk = blockIdx.x;
    int tid = threadIdx.x;
    if (blk < 128) {
        int eid = blk * 256 + tid;          // [0, 32768)
        int kc = eid >> 13;
        int n = (eid >> 6) & 127;
        int kk = eid & 63;
        float wv = We1[(2 * NODE_DIM + kc * 64 + kk) * EDGE_DIM + n];
        g_Bimg1[(size_t)kc * 8192 + n * 64 + kk] = __float2half_rn(wv);
    } else if (blk < 192) {
        int eid = (blk - 128) * 256 + tid;  // [0, 16384)
        int kc = eid >> 13;
        int n = (eid >> 6) & 127;
        int kk = eid & 63;
        float wv = We2[(kc * 64 + kk) * EDGE_DIM + n];
        g_Bimg2[(size_t)kc * 8192 + n * 64 + kk] = __float2half_rn(wv);
    } else if (blk < 704) {
        __shared__ float x[2][NODE_DIM];
        int sub = tid >> 7;                 // 0/1: node within block
        int i = (blk - 192) * 2 + sub;      // [0, 1024)
        int d = tid & 127;
        const float* src;
        const float* W;
        float* dst;
        float acc;
        if (i < N_A) {
            src = na + i * NODE_DIM;
            dst = g_aproj + i * EDGE_DIM;
            W = We1;
            acc = be1[d];
            g_suma[i * EDGE_DIM + d] = 0.f;
        } else {
            int j = i - N_A;
            src = nb + j * NODE_DIM;
            dst = g_bproj + j * EDGE_DIM;
            W = We1 + NODE_DIM * EDGE_DIM;
            acc = 0.f;
            g_sumb[j * EDGE_DIM + d] = 0.f;
        }
        x[sub][d] = src[d];
        __syncthreads();
#pragma unroll 8
        for (int k = 0; k < NODE_DIM; k++) acc = fmaf(x[sub][k], W[k * EDGE_DIM + d], acc);
        dst[d] = acc;
        if (i >= N_A) g_bprojh[(i - N_A) * EDGE_DIM + d] = __float2half_rn(acc);
    } else if (blk < 832) {
        int eid = (blk - 704) * 256 + tid;  // [0, 32768)
        int kc = eid >> 13;
        int n = (eid >> 6) & 127;
        int kk = eid & 63;
        float wv = Wn1[(kc * 64 + kk) * NODE_DIM + n];
        g_Wn1img[(size_t)kc * 8192 + n * 64 + kk] = __float2half_rn(wv);
    } else {
        int eid = (blk - 832) * 256 + tid;  // [0, 16384)
        int kc = eid >> 13;
        int n = (eid >> 6) & 127;
        int kk = eid & 63;
        float wv = Wn2[(kc * 64 + kk) * NODE_DIM + n];
        g_Wn2img[(size_t)kc * 8192 + n * 64 + kk] = __float2half_rn(wv);
    }
}

// ---------------------------------------------------------------------------
// Fused edge pipeline (R7-proven mainloop), single-pass fp16, 2 CTAs/SM.
// 8 warps (4x2): warp tile 32 x 64. One 128x128 edge tile per CTA.
// Accumulates suma partials via one 128-float atomicAdd per CTA.
// ---------------------------------------------------------------------------
__global__ void __launch_bounds__(256, 2) fused_kernel(const float* __restrict__ edge,
                                                       const float* __restrict__ be2,
                                                       float* __restrict__ out) {
    extern __shared__ __align__(128) char smem_c[];
    const uint32_t sb = smem_u32(smem_c);
    const int tid = threadIdx.x;
    const int wid = tid >> 5;
    const int lane = tid & 31;
    const int wm = wid >> 1;
    const int wn = wid & 1;
    const int m0 = blockIdx.x * 128;
    const int a_idx = m0 >> 9;
    const int b0 = m0 & (N_B - 1);

    const uint32_t a_loff = (uint32_t)(wm * 32 + (lane & 15)) * RSTRIDE + ((lane >> 4) << 4);
    const uint32_t b_loff = (uint32_t)(wn * 64 + (lane & 7) + ((lane >> 4) << 3)) * RSTRIDE +
                            (((lane >> 3) & 1) << 4);

    // ---- Prologue: B chunk0 via cp.async; A chunk0 via LDG ----
    {
        const char* src = (const char*)g_Bimg1;
#pragma unroll
        for (int i = 0; i < 4; i++) {
            int idx = tid + i * 256;
            int n = idx >> 3;
            int p = idx & 7;
            CP_ASYNC16(sb + BS_OFF + n * RSTRIDE + p * 16, src + (size_t)idx * 16);
        }
        CP_COMMIT();
    }
    float4 regsA[8];
    {
        const float* Ag = edge + (size_t)m0 * 256;
#pragma unroll
        for (int i = 0; i < 8; i++) {
            int idx = tid + i * 256;
            regsA[i] = *(const float4*)(Ag + (size_t)(idx >> 4) * 256 + (idx & 15) * 4);
        }
    }

    float acc[2][8][4];
#pragma unroll
    for (int mt = 0; mt < 2; mt++)
#pragma unroll
        for (int nt = 0; nt < 8; nt++)
#pragma unroll
            for (int q = 0; q < 4; q++) acc[mt][nt][q] = 0.f;

    // ================= GEMM1: edge_tile @ We (K=256, 4 chunks) ==============
    for (int kc = 0; kc < 4; kc++) {
        const int buf = kc & 1;
        // convert + store A chunk kc (fp32 -> fp16)
#pragma unroll
        for (int i = 0; i < 8; i++) {
            int idx = tid + i * 256;
            int row = idx >> 4;
            int f4 = idx & 15;
            float4 v = regsA[i];
            __half2 h01 = __floats2half2_rn(v.x, v.y);
            __half2 h23 = __floats2half2_rn(v.z, v.w);
            *(uint2*)(smem_c + AS_OFF + buf * BLK + (uint32_t)row * RSTRIDE + f4 * 8) =
                make_uint2(*reinterpret_cast<uint32_t*>(&h01),
                           *reinterpret_cast<uint32_t*>(&h23));
        }
        CP_WAIT_ALL();     // B chunk kc landed
        __syncthreads();
        if (kc < 3) {
            // prefetch B chunk kc+1; LDG A chunk kc+1
            const char* srcB = (const char*)(g_Bimg1 + (size_t)(kc + 1) * 8192);
#pragma unroll
            for (int i = 0; i < 4; i++) {
                int idx = tid + i * 256;
                int n = idx >> 3;
                int p = idx & 7;
                CP_ASYNC16(sb + BS_OFF + (buf ^ 1) * BLK + n * RSTRIDE + p * 16,
                           srcB + (size_t)idx * 16);
            }
            CP_COMMIT();
            const float* Ag = edge + (size_t)m0 * 256 + (kc + 1) * 64;
#pragma unroll
            for (int i = 0; i < 8; i++) {
                int idx = tid + i * 256;
                regsA[i] = *(const float4*)(Ag + (size_t)(idx >> 4) * 256 + (idx & 15) * 4);
            }
        } else {
            // kc==3: BS buf0 (chunk2) fully consumed -> prefetch We2 chunk0
            const char* srcW = (const char*)g_Bimg2;
#pragma unroll
            for (int i = 0; i < 4; i++) {
                int idx = tid + i * 256;
                int n = idx >> 3;
                int p = idx & 7;
                CP_ASYNC16(sb + BS_OFF + 0 * BLK + n * RSTRIDE + p * 16,
                           srcW + (size_t)idx * 16);
            }
            CP_COMMIT();
        }
        // MMA over chunk kc
#pragma unroll
        for (int ks = 0; ks < 4; ks++) {
            const uint32_t kb = ks << 5;
            const uint32_t aB = sb + AS_OFF + buf * BLK + a_loff + kb;
            const uint32_t bB = sb + BS_OFF + buf * BLK + b_loff + kb;
            uint32_t af[2][4];
            ldsm_x4(aB, af[0]);
            ldsm_x4(aB + 16 * RSTRIDE, af[1]);
#pragma unroll
            for (int np = 0; np < 4; np++) {
                uint32_t bf[4];
                ldsm_x4(bB + np * 16 * RSTRIDE, bf);
#pragma unroll
                for (int mt = 0; mt < 2; mt++) {
                    mma_f16(acc[mt][2 * np], af[mt], bf[0], bf[1]);
                    mma_f16(acc[mt][2 * np + 1], af[mt], bf[2], bf[3]);
                }
            }
        }
    }
    // All GEMM1 reads of AS/BS retire before h / We2 overwrite them.
    __syncthreads();

    // We2 chunk1 -> BS buf1
    {
        const char* srcW = (const char*)(g_Bimg2 + 8192);
#pragma unroll
        for (int i = 0; i < 4; i++) {
            int idx = tid + i * 256;
            int n = idx >> 3;
            int p = idx & 7;
            CP_ASYNC16(sb + BS_OFF + 1 * BLK + n * RSTRIDE + p * 16, srcW + (size_t)idx * 16);
        }
        CP_COMMIT();
    }

    // ---- Epilogue 1: h = relu(D + aproj + bproj) -> fp16 images in AS bufs ----
    {
        const int qrow = lane >> 2;
        const int qcol = (lane & 3) * 2;
#pragma unroll
        for (int mt = 0; mt < 2; mt++) {
            int r_base = wm * 32 + mt * 16 + qrow;
#pragma unroll
            for (int nt = 0; nt < 8; nt++) {
                int col = wn * 64 + nt * 8 + qcol;
                float2 ap = __ldg((const float2*)(g_aproj + a_idx * 128 + col));
#pragma unroll
                for (int hf = 0; hf < 2; hf++) {
                    int row = r_base + 8 * hf;
                    __half2 bph = *(const __half2*)(g_bprojh + (size_t)(b0 + row) * 128 + col);
                    float2 bp = __half22float2(bph);
                    float v0 = fmaxf(acc[mt][nt][2 * hf] + ap.x + bp.x, 0.f);
                    float v1 = fmaxf(acc[mt][nt][2 * hf + 1] + ap.y + bp.y, 0.f);
                    __half2 h01 = __floats2half2_rn(v0, v1);
                    int ch = col >> 6;
                    *(uint32_t*)(smem_c + AS_OFF + ch * BLK + (uint32_t)row * RSTRIDE +
                                 (col & 63) * 2) = *reinterpret_cast<uint32_t*>(&h01);
                    acc[mt][nt][2 * hf] = 0.f;
                    acc[mt][nt][2 * hf + 1] = 0.f;
                }
            }
        }
    }
    CP_WAIT_ALL();   // We2 chunks landed
    __syncthreads();

    // ================= GEMM2: h @ We2 (K=128, 2 chunks) =====================
#pragma unroll
    for (int ch = 0; ch < 2; ch++) {
#pragma unroll
        for (int ks = 0; ks < 4; ks++) {
            const uint32_t kb = ks << 5;
            const uint32_t aB = sb + AS_OFF + ch * BLK + a_loff + kb;
            const uint32_t bB = sb + BS_OFF + ch * BLK + b_loff + kb;
            uint32_t af[2][4];
            ldsm_x4(aB, af[0]);
            ldsm_x4(aB + 16 * RSTRIDE, af[1]);
#pragma unroll
            for (int np = 0; np < 4; np++) {
                uint32_t bf[4];
                ldsm_x4(bB + np * 16 * RSTRIDE, bf);
#pragma unroll
                for (int mt = 0; mt < 2; mt++) {
                    mma_f16(acc[mt][2 * np], af[mt], bf[0], bf[1]);
                    mma_f16(acc[mt][2 * np + 1], af[mt], bf[2], bf[3]);
                }
            }
        }
    }

    // ---- Epilogue 2: out = relu(D + be2); accumulate suma partials ----
    {
        float* wsumS = (float*)(smem_c + WSUM_OFF);  // [8 warps][64]
        const int qrow = lane >> 2;
        const int qc = lane & 3;
#pragma unroll
        for (int nt = 0; nt < 8; nt++) {
            int col = wn * 64 + nt * 8 + qc * 2;
            float2 bz = __ldg((const float2*)(be2 + col));
            float p0 = 0.f, p1 = 0.f;
#pragma unroll
            for (int mt = 0; mt < 2; mt++) {
                int r_base = wm * 32 + mt * 16 + qrow;
#pragma unroll
                for (int hf = 0; hf < 2; hf++) {
                    int row = r_base + 8 * hf;
                    float2 w;
                    w.x = fmaxf(acc[mt][nt][2 * hf] + bz.x, 0.f);
                    w.y = fmaxf(acc[mt][nt][2 * hf + 1] + bz.y, 0.f);
                    *(float2*)(out + (size_t)(m0 + row) * 128 + col) = w;
                    p0 += w.x;
                    p1 += w.y;
                }
            }
            p0 += __shfl_xor_sync(0xffffffffu, p0, 4);
            p0 += __shfl_xor_sync(0xffffffffu, p0, 8);
            p0 += __shfl_xor_sync(0xffffffffu, p0, 16);
            p1 += __shfl_xor_sync(0xffffffffu, p1, 4);
            p1 += __shfl_xor_sync(0xffffffffu, p1, 8);
            p1 += __shfl_xor_sync(0xffffffffu, p1, 16);
            if (lane < 4) {
                wsumS[wid * 64 + nt * 8 + lane * 2] = p0;
                wsumS[wid * 64 + nt * 8 + lane * 2 + 1] = p1;
            }
        }
        __syncthreads();
        if (tid < 128) {
            int wn2 = tid >> 6;
            int off = tid & 63;
            float s = wsumS[(0 * 2 + wn2) * 64 + off] + wsumS[(1 * 2 + wn2) * 64 + off] +
                      wsumS[(2 * 2 + wn2) * 64 + off] + wsumS[(3 * 2 + wn2) * 64 + off];
            atomicAdd(g_suma + a_idx * 128 + tid, s);
        }
    }
}

// ---------------------------------------------------------------------------
// K4: column sums (over a) -> g_sumb, 4-way split over a + atomics.
// ---------------------------------------------------------------------------
__global__ void __launch_bounds__(256) sum_b_kernel(const float* __restrict__ lat) {
    __shared__ float4 red[8][33];
    int b = blockIdx.x & (N_B - 1);
    int as = blockIdx.x >> 9;           // a-slice [as*128, as*128+128)
    int d4 = threadIdx.x & 31;
    int g = threadIdx.x >> 5;
    float x = 0.f, y = 0.f, z = 0.f, w = 0.f;
    const float4* p = (const float4*)lat + (size_t)b * 32;
    int a_end = as * 128 + 128;
    for (int a2 = as * 128 + g; a2 < a_end; a2 += 8) {
        float4 v = p[(size_t)a2 * (N_B * 32) + d4];
        x += v.x; y += v.y; z += v.z; w += v.w;
    }
    red[g][d4] = make_float4(x, y, z, w);
    __syncthreads();
    if (g == 0) {
#pragma unroll
        for (int k = 1; k < 8; k++) {
            float4 v = red[k][d4];
            x += v.x; y += v.y; z += v.z; w += v.w;
        }
        float* dst = g_sumb + b * EDGE_DIM + d4 * 4;
        atomicAdd(dst + 0, x);
        atomicAdd(dst + 1, y);
        atomicAdd(dst + 2, z);
        atomicAdd(dst + 3, w);
    }
}

// ---------------------------------------------------------------------------
// K5: node MLPs via the same tensor-core pipeline. Grid 8: tiles of 128
// nodes (blk 0-3 = nodes_a, 4-7 = nodes_b). A rows = [emb | suma/sumb]
// (K=256: chunks 0-1 from embeds, 2-3 from sums). B = Wn1/Wn2 fp16 images.
// ---------------------------------------------------------------------------
__global__ void __launch_bounds__(256, 2) node_gemm_kernel(const float* __restrict__ na,
                                                           const float* __restrict__ nb,
                                                           const float* __restrict__ bn1,
                                                           const float* __restrict__ bn2,
                                                           float* __restrict__ out_nodes) {
    extern __shared__ __align__(128) char smem_c[];
    const uint32_t sb = smem_u32(smem_c);
    const int tid = threadIdx.x;
    const int wid = tid >> 5;
    const int lane = tid & 31;
    const int wm = wid >> 1;
    const int wn = wid & 1;
    const int blk = blockIdx.x;

    const float* embBase;
    const float* sumBase;
    if (blk < 4) {
        embBase = na + (size_t)blk * 128 * 128;
        sumBase = g_suma + (size_t)blk * 128 * 128;
    } else {
        embBase = nb + (size_t)(blk - 4) * 128 * 128;
        sumBase = g_sumb + (size_t)(blk - 4) * 128 * 128;
    }

    const uint32_t a_loff = (uint32_t)(wm * 32 + (lane & 15)) * RSTRIDE + ((lane >> 4) << 4);
    const uint32_t b_loff = (uint32_t)(wn * 64 + (lane & 7) + ((lane >> 4) << 3)) * RSTRIDE +
                            (((lane >> 3) & 1) << 4);

    // Prologue: Wn1 chunk0
    {
        const char* src = (const char*)g_Wn1img;
#pragma unroll
        for (int i = 0; i < 4; i++) {
            int idx = tid + i * 256;
            int n = idx >> 3;
            int p = idx & 7;
            CP_ASYNC16(sb + BS_OFF + n * RSTRIDE + p * 16, src + (size_t)idx * 16);
        }
        CP_COMMIT();
    }
    float4 regsA[8];
    {
        const float* Ag = embBase;   // chunk0: emb cols 0-63
#pragma unroll
        for (int i = 0; i < 8; i++) {
            int idx = tid + i * 256;
            regsA[i] = *(const float4*)(Ag + (size_t)(idx >> 4) * 128 + (idx & 15) * 4);
        }
    }

    float acc[2][8][4];
#pragma unroll
    for (int mt = 0; mt < 2; mt++)
#pragma unroll
        for (int nt = 0; nt < 8; nt++)
#pragma unroll
            for (int q = 0; q < 4; q++) acc[mt][nt][q] = 0.f;

    // GEMM1: [emb|sum] @ Wn1 (K=256, 4 chunks)
    for (int kc = 0; kc < 4; kc++) {
        const int buf = kc & 1;
#pragma unroll
        for (int i = 0; i < 8; i++) {
            int idx = tid + i * 256;
            int row = idx >> 4;
            int f4 = idx & 15;
            float4 v = regsA[i];
            __half2 h01 = __floats2half2_rn(v.x, v.y);
            __half2 h23 = __floats2half2_rn(v.z, v.w);
            *(uint2*)(smem_c + AS_OFF + buf * BLK + (uint32_t)row * RSTRIDE + f4 * 8) =
                make_uint2(*reinterpret_cast<uint32_t*>(&h01),
                           *reinterpret_cast<uint32_t*>(&h23));
        }
        CP_WAIT_ALL();
        __syncthreads();
        if (kc < 3) {
            const char* srcB = (const char*)(g_Wn1img + (size_t)(kc + 1) * 8192);
#pragma unroll
            for (int i = 0; i < 4; i++) {
                int idx = tid + i * 256;
                int n = idx >> 3;
                int p = idx & 7;
                CP_ASYNC16(sb + BS_OFF + (buf ^ 1) * BLK + n * RSTRIDE + p * 16,
                           srcB + (size_t)idx * 16);
            }
            CP_COMMIT();
            // A chunk kc+1: kc+1 in {1,2,3}; 1 -> emb cols 64-127, 2/3 -> sums
            const float* Ag = (kc + 1 < 2) ? (embBase + 64)
                                           : (sumBase + (kc + 1 - 2) * 64);
#pragma unroll
            for (int i = 0; i < 8; i++) {
                int idx = tid + i * 256;
                regsA[i] = *(const float4*)(Ag + (size_t)(idx >> 4) * 128 + (idx & 15) * 4);
            }
        } else {
            const char* srcW = (const char*)g_Wn2img;
#pragma unroll
            for (int i = 0; i < 4; i++) {
                int idx = tid + i * 256;
                int n = idx >> 3;
                int p = idx & 7;
                CP_ASYNC16(sb + BS_OFF + 0 * BLK + n * RSTRIDE + p * 16,
                           srcW + (size_t)idx * 16);
            }
            CP_COMMIT();
        }
#pragma unroll
        for (int ks = 0; ks < 4; ks++) {
            const uint32_t kb = ks << 5;
            const uint32_t aB = sb + AS_OFF + buf * BLK + a_loff + kb;
            const uint32_t bB = sb + BS_OFF + buf * BLK + b_loff + kb;
            uint32_t af[2][4];
            ldsm_x4(aB, af[0]);
            ldsm_x4(aB + 16 * RSTRIDE, af[1]);
#pragma unroll
            for (int np = 0; np < 4; np++) {
                uint32_t bf[4];
                ldsm_x4(bB + np * 16 * RSTRIDE, bf);
#pragma unroll
                for (int mt = 0; mt < 2; mt++) {
                    mma_f16(acc[mt][2 * np], af[mt], bf[0], bf[1]);
                    mma_f16(acc[mt][2 * np + 1], af[mt], bf[2], bf[3]);
                }
            }
        }
    }
    __syncthreads();

    // Wn2 chunk1 -> BS buf1
    {
        const char* srcW = (const char*)(g_Wn2img + 8192);
#pragma unroll
        for (int i = 0; i < 4; i++) {
            int idx = tid + i * 256;
            int n = idx >> 3;
            int p = idx & 7;
            CP_ASYNC16(sb + BS_OFF + 1 * BLK + n * RSTRIDE + p * 16, srcW + (size_t)idx * 16);
        }
        CP_COMMIT();
    }

    // Epilogue 1: hmid = relu(D + bn1) -> fp16 images in AS bufs
    {
        const int qrow = lane >> 2;
        const int qcol = (lane & 3) * 2;
#pragma unroll
        for (int mt = 0; mt < 2; mt++) {
            int r_base = wm * 32 + mt * 16 + qrow;
#pragma unroll
            for (int nt = 0; nt < 8; nt++) {
                int col = wn * 64 + nt * 8 + qcol;
                float2 bz = __ldg((const float2*)(bn1 + col));
#pragma unroll
                for (int hf = 0; hf < 2; hf++) {
                    int row = r_base + 8 * hf;
                    float v0 = fmaxf(acc[mt][nt][2 * hf] + bz.x, 0.f);
                    float v1 = fmaxf(acc[mt][nt][2 * hf + 1] + bz.y, 0.f);
                    __half2 h01 = __floats2half2_rn(v0, v1);
                    int ch = col >> 6;
                    *(uint32_t*)(smem_c + AS_OFF + ch * BLK + (uint32_t)row * RSTRIDE +
                                 (col & 63) * 2) = *reinterpret_cast<uint32_t*>(&h01);
                    acc[mt][nt][2 * hf] = 0.f;
                    acc[mt][nt][2 * hf + 1] = 0.f;
                }
            }
        }
    }
    CP_WAIT_ALL();
    __syncthreads();

    // GEMM2: hmid @ Wn2 (K=128, 2 chunks)
#pragma unroll
    for (int ch = 0; ch < 2; ch++) {
#pragma unroll
        for (int ks = 0; ks < 4; ks++) {
            const uint32_t kb = ks << 5;
            const uint32_t aB = sb + AS_OFF + ch * BLK + a_loff + kb;
            const uint32_t bB = sb + BS_OFF + ch * BLK + b_loff + kb;
            uint32_t af[2][4];
            ldsm_x4(aB, af[0]);
            ldsm_x4(aB + 16 * RSTRIDE, af[1]);
#pragma unroll
            for (int np = 0; np < 4; np++) {
                uint32_t bf[4];
                ldsm_x4(bB + np * 16 * RSTRIDE, bf);
#pragma unroll
                for (int mt = 0; mt < 2; mt++) {
                    mma_f16(acc[mt][2 * np], af[mt], bf[0], bf[1]);
                    mma_f16(acc[mt][2 * np + 1], af[mt], bf[2], bf[3]);
                }
            }
        }
    }

    // Epilogue 2: out = relu(D + bn2)
    {
        const int qrow = lane >> 2;
        const int qcol = (lane & 3) * 2;
        const int r0g = blk * 128;
#pragma unroll
        for (int mt = 0; mt < 2; mt++) {
            int r_base = wm * 32 + mt * 16 + qrow;
#pragma unroll
            for (int nt = 0; nt < 8; nt++) {
                int col = wn * 64 + nt * 8 + qcol;
                float2 bz = __ldg((const float2*)(bn2 + col));
#pragma unroll
                for (int hf = 0; hf < 2; hf++) {
                    int row = r_base + 8 * hf;
                    float2 w;
                    w.x = fmaxf(acc[mt][nt][2 * hf] + bz.x, 0.f);
                    w.y = fmaxf(acc[mt][nt][2 * hf + 1] + bz.y, 0.f);
                    *(float2*)(out_nodes + (size_t)(r0g + row) * 128 + col) = w;
                }
            }
        }
    }
}

// ---------------------------------------------------------------------------
extern "C" void kernel_launch(void* const* d_in, const int* in_sizes, int n_in,
                              void* d_out, int out_size) {
    const float* edge = (const float*)d_in[0];
    const float* na   = (const float*)d_in[1];
    const float* nb   = (const float*)d_in[2];
    const float* We1  = (const float*)d_in[3];
    const float* be1  = (const float*)d_in[4];
    const float* We2  = (const float*)d_in[5];
    const float* be2  = (const float*)d_in[6];
    const float* Wn1  = (const float*)d_in[7];
    const float* bn1  = (const float*)d_in[8];
    const float* Wn2  = (const float*)d_in[9];
    const float* bn2  = (const float*)d_in[10];
    float* out = (float*)d_out;

    static int smem_set = 0;
    if (!smem_set) {
        cudaFuncSetAttribute(fused_kernel, cudaFuncAttributeMaxDynamicSharedMemorySize,
                             SMEM_BYTES);
        cudaFuncSetAttribute(node_gemm_kernel, cudaFuncAttributeMaxDynamicSharedMemorySize,
                             SMEM_BYTES);
        smem_set = 1;
    }

    init_kernel<<<896, 256>>>(We1, We2, na, nb, be1, Wn1, Wn2);
    fused_kernel<<<M_EDGES / 128, 256, SMEM_BYTES>>>(edge, be2, out);
    sum_b_kernel<<<4 * N_B, 256>>>(out);
    node_gemm_kernel<<<8, 256, SMEM_BYTES>>>(na, nb, bn1, bn2,
                                             out + (size_t)M_EDGES * EDGE_DIM);
}

// round 12
// speedup vs baseline: 1.3679x; 1.0363x over previous
#include <cuda_runtime.h>
#include <cuda_fp16.h>
#include <cstdint>
#include <cstddef>

#define NODE_DIM 128
#define EDGE_DIM 128
#define N_A 512
#define N_B 512
#define M_EDGES (N_A * N_B)

// ---------------------------------------------------------------------------
// Device scratch
// ---------------------------------------------------------------------------
__device__ float g_aproj[N_A * EDGE_DIM];     // nodes_a @ Wa + be1
__device__ float g_bproj[N_B * EDGE_DIM];     // nodes_b @ Wb (fp32)
__device__ __half g_bprojh[N_B * EDGE_DIM];   // fp16 copy for fused epilogue
__device__ float g_suma[N_A * EDGE_DIM];      // accumulated by fused kernel
__device__ float g_sumb[N_B * EDGE_DIM];      // accumulated by sum_b kernel
// Pre-transposed fp16 weight images: [chunk][n(128)][k(64)]
__device__ __half g_Bimg1[4 * 8192];   // We  (256x128): 4 K-chunks
__device__ __half g_Bimg2[2 * 8192];   // We2 (128x128): 2 K-chunks
__device__ __half g_Wn1img[4 * 8192];  // Wn1 (256x128): 4 K-chunks
__device__ __half g_Wn2img[2 * 8192];  // Wn2 (128x128): 2 K-chunks

// ---------------------------------------------------------------------------
// PTX helpers (compute_80+ only)
// ---------------------------------------------------------------------------
__device__ __forceinline__ uint32_t smem_u32(const void* p) {
    uint32_t a;
    asm("{ .reg .u64 t; cvta.to.shared.u64 t, %1; cvt.u32.u64 %0, t; }" : "=r"(a) : "l"(p));
    return a;
}
__device__ __forceinline__ void ldsm_x4(uint32_t addr, uint32_t* r) {
    asm volatile("ldmatrix.sync.aligned.m8n8.x4.shared.b16 {%0,%1,%2,%3}, [%4];"
                 : "=r"(r[0]), "=r"(r[1]), "=r"(r[2]), "=r"(r[3]) : "r"(addr));
}
__device__ __forceinline__ void mma_f16(float* c, const uint32_t* a, uint32_t b0, uint32_t b1) {
    asm volatile(
        "mma.sync.aligned.m16n8k16.row.col.f32.f16.f16.f32 "
        "{%0,%1,%2,%3}, {%4,%5,%6,%7}, {%8,%9}, {%0,%1,%2,%3};"
        : "+f"(c[0]), "+f"(c[1]), "+f"(c[2]), "+f"(c[3])
        : "r"(a[0]), "r"(a[1]), "r"(a[2]), "r"(a[3]), "r"(b0), "r"(b1));
}
#define CP_ASYNC16(dst, src) \
    asm volatile("cp.async.cg.shared.global [%0], [%1], 16;" :: "r"(dst), "l"(src))
#define CP_COMMIT() asm volatile("cp.async.commit_group;" ::: "memory")
#define CP_WAIT_ALL() asm volatile("cp.async.wait_group 0;" ::: "memory")

// SMEM layout. Padded row stride: 72 fp16 = 144 B (conflict-free ldmatrix).
#define RSTRIDE 144
#define BLK 18432                   /* one [128][72] b16 image */
#define AS_OFF 0                    /* A bufs 0,1 -> later h chunks 0,1   */
#define BS_OFF (2 * BLK)            /* B bufs 0,1 -> later We2 chunks 0,1 */
#define WSUM_OFF (4 * BLK)          /* 8 warps x 64 floats = 2 KB         */
#define SMEM_BYTES (4 * BLK + 2048) /* 75776 -> 2 CTAs/SM                 */

// ---------------------------------------------------------------------------
// init: [0,128) Bimg1; [128,192) Bimg2; [192,320) Wn1img; [320,384) Wn2img;
//       [384,1408): projections, 1 node/block, k-split in half + zero sums.
// ---------------------------------------------------------------------------
__global__ void __launch_bounds__(256) init_kernel(const float* __restrict__ We1,
                                                   const float* __restrict__ We2,
                                                   const float* __restrict__ na,
                                                   const float* __restrict__ nb,
                                                   const float* __restrict__ be1,
                                                   const float* __restrict__ Wn1,
                                                   const float* __restrict__ Wn2) {
    int blk = blockIdx.x;
    int tid = threadIdx.x;
    if (blk < 128) {
        int eid = blk * 256 + tid;          // [0, 32768)
        int kc = eid >> 13;
        int n = (eid >> 6) & 127;
        int kk = eid & 63;
        float wv = We1[(2 * NODE_DIM + kc * 64 + kk) * EDGE_DIM + n];
        g_Bimg1[(size_t)kc * 8192 + n * 64 + kk] = __float2half_rn(wv);
    } else if (blk < 192) {
        int eid = (blk - 128) * 256 + tid;  // [0, 16384)
        int kc = eid >> 13;
        int n = (eid >> 6) & 127;
        int kk = eid & 63;
        float wv = We2[(kc * 64 + kk) * EDGE_DIM + n];
        g_Bimg2[(size_t)kc * 8192 + n * 64 + kk] = __float2half_rn(wv);
    } else if (blk < 320) {
        int eid = (blk - 192) * 256 + tid;  // [0, 32768)
        int kc = eid >> 13;
        int n = (eid >> 6) & 127;
        int kk = eid & 63;
        float wv = Wn1[(kc * 64 + kk) * NODE_DIM + n];
        g_Wn1img[(size_t)kc * 8192 + n * 64 + kk] = __float2half_rn(wv);
    } else if (blk < 384) {
        int eid = (blk - 320) * 256 + tid;  // [0, 16384)
        int kc = eid >> 13;
        int n = (eid >> 6) & 127;
        int kk = eid & 63;
        float wv = Wn2[(kc * 64 + kk) * NODE_DIM + n];
        g_Wn2img[(size_t)kc * 8192 + n * 64 + kk] = __float2half_rn(wv);
    } else {
        __shared__ float x[NODE_DIM];
        __shared__ float part[256];
        int i = blk - 384;                  // [0, 1024)
        int d = tid & 127;
        int half = tid >> 7;
        const float* src;
        const float* W;
        if (i < N_A) {
            src = na + i * NODE_DIM;
            W = We1;
        } else {
            src = nb + (i - N_A) * NODE_DIM;
            W = We1 + NODE_DIM * EDGE_DIM;
        }
        if (tid < 128) x[tid] = src[tid];
        __syncthreads();
        float acc = 0.f;
        const float* Wp = W + (half * 64) * EDGE_DIM + d;
        const float* xp = x + half * 64;
#pragma unroll 8
        for (int k = 0; k < 64; k++) acc = fmaf(xp[k], Wp[k * EDGE_DIM], acc);
        part[tid] = acc;
        __syncthreads();
        if (half == 0) {
            float v = part[d] + part[d + 128];
            if (i < N_A) {
                g_aproj[i * EDGE_DIM + d] = v + be1[d];
                g_suma[i * EDGE_DIM + d] = 0.f;
            } else {
                int j = i - N_A;
                g_bproj[j * EDGE_DIM + d] = v;
                g_bprojh[j * EDGE_DIM + d] = __float2half_rn(v);
                g_sumb[j * EDGE_DIM + d] = 0.f;
            }
        }
    }
}

// ---------------------------------------------------------------------------
// Fused edge pipeline (R7-proven mainloop), single-pass fp16, 2 CTAs/SM.
// 8 warps (4x2): warp tile 32 x 64. One 128x128 edge tile per CTA.
// Accumulates suma partials via one 128-float atomicAdd per CTA.
// ---------------------------------------------------------------------------
__global__ void __launch_bounds__(256, 2) fused_kernel(const float* __restrict__ edge,
                                                       const float* __restrict__ be2,
                                                       float* __restrict__ out) {
    extern __shared__ __align__(128) char smem_c[];
    const uint32_t sb = smem_u32(smem_c);
    const int tid = threadIdx.x;
    const int wid = tid >> 5;
    const int lane = tid & 31;
    const int wm = wid >> 1;
    const int wn = wid & 1;
    const int m0 = blockIdx.x * 128;
    const int a_idx = m0 >> 9;
    const int b0 = m0 & (N_B - 1);

    const uint32_t a_loff = (uint32_t)(wm * 32 + (lane & 15)) * RSTRIDE + ((lane >> 4) << 4);
    const uint32_t b_loff = (uint32_t)(wn * 64 + (lane & 7) + ((lane >> 4) << 3)) * RSTRIDE +
                            (((lane >> 3) & 1) << 4);

    // ---- Prologue: B chunk0 via cp.async; A chunk0 via LDG ----
    {
        const char* src = (const char*)g_Bimg1;
#pragma unroll
        for (int i = 0; i < 4; i++) {
            int idx = tid + i * 256;
            int n = idx >> 3;
            int p = idx & 7;
            CP_ASYNC16(sb + BS_OFF + n * RSTRIDE + p * 16, src + (size_t)idx * 16);
        }
        CP_COMMIT();
    }
    float4 regsA[8];
    {
        const float* Ag = edge + (size_t)m0 * 256;
#pragma unroll
        for (int i = 0; i < 8; i++) {
            int idx = tid + i * 256;
            regsA[i] = *(const float4*)(Ag + (size_t)(idx >> 4) * 256 + (idx & 15) * 4);
        }
    }

    float acc[2][8][4];
#pragma unroll
    for (int mt = 0; mt < 2; mt++)
#pragma unroll
        for (int nt = 0; nt < 8; nt++)
#pragma unroll
            for (int q = 0; q < 4; q++) acc[mt][nt][q] = 0.f;

    // ================= GEMM1: edge_tile @ We (K=256, 4 chunks) ==============
    for (int kc = 0; kc < 4; kc++) {
        const int buf = kc & 1;
        // convert + store A chunk kc (fp32 -> fp16)
#pragma unroll
        for (int i = 0; i < 8; i++) {
            int idx = tid + i * 256;
            int row = idx >> 4;
            int f4 = idx & 15;
            float4 v = regsA[i];
            __half2 h01 = __floats2half2_rn(v.x, v.y);
            __half2 h23 = __floats2half2_rn(v.z, v.w);
            *(uint2*)(smem_c + AS_OFF + buf * BLK + (uint32_t)row * RSTRIDE + f4 * 8) =
                make_uint2(*reinterpret_cast<uint32_t*>(&h01),
                           *reinterpret_cast<uint32_t*>(&h23));
        }
        CP_WAIT_ALL();     // B chunk kc landed
        __syncthreads();
        if (kc < 3) {
            // prefetch B chunk kc+1; LDG A chunk kc+1
            const char* srcB = (const char*)(g_Bimg1 + (size_t)(kc + 1) * 8192);
#pragma unroll
            for (int i = 0; i < 4; i++) {
                int idx = tid + i * 256;
                int n = idx >> 3;
                int p = idx & 7;
                CP_ASYNC16(sb + BS_OFF + (buf ^ 1) * BLK + n * RSTRIDE + p * 16,
                           srcB + (size_t)idx * 16);
            }
            CP_COMMIT();
            const float* Ag = edge + (size_t)m0 * 256 + (kc + 1) * 64;
#pragma unroll
            for (int i = 0; i < 8; i++) {
                int idx = tid + i * 256;
                regsA[i] = *(const float4*)(Ag + (size_t)(idx >> 4) * 256 + (idx & 15) * 4);
            }
        } else {
            // kc==3: BS buf0 (chunk2) fully consumed -> prefetch We2 chunk0
            const char* srcW = (const char*)g_Bimg2;
#pragma unroll
            for (int i = 0; i < 4; i++) {
                int idx = tid + i * 256;
                int n = idx >> 3;
                int p = idx & 7;
                CP_ASYNC16(sb + BS_OFF + 0 * BLK + n * RSTRIDE + p * 16,
                           srcW + (size_t)idx * 16);
            }
            CP_COMMIT();
        }
        // MMA over chunk kc
#pragma unroll
        for (int ks = 0; ks < 4; ks++) {
            const uint32_t kb = ks << 5;
            const uint32_t aB = sb + AS_OFF + buf * BLK + a_loff + kb;
            const uint32_t bB = sb + BS_OFF + buf * BLK + b_loff + kb;
            uint32_t af[2][4];
            ldsm_x4(aB, af[0]);
            ldsm_x4(aB + 16 * RSTRIDE, af[1]);
#pragma unroll
            for (int np = 0; np < 4; np++) {
                uint32_t bf[4];
                ldsm_x4(bB + np * 16 * RSTRIDE, bf);
#pragma unroll
                for (int mt = 0; mt < 2; mt++) {
                    mma_f16(acc[mt][2 * np], af[mt], bf[0], bf[1]);
                    mma_f16(acc[mt][2 * np + 1], af[mt], bf[2], bf[3]);
                }
            }
        }
    }
    // All GEMM1 reads of AS/BS retire before h / We2 overwrite them.
    __syncthreads();

    // We2 chunk1 -> BS buf1
    {
        const char* srcW = (const char*)(g_Bimg2 + 8192);
#pragma unroll
        for (int i = 0; i < 4; i++) {
            int idx = tid + i * 256;
            int n = idx >> 3;
            int p = idx & 7;
            CP_ASYNC16(sb + BS_OFF + 1 * BLK + n * RSTRIDE + p * 16, srcW + (size_t)idx * 16);
        }
        CP_COMMIT();
    }

    // ---- Epilogue 1: h = relu(D + aproj + bproj) -> fp16 images in AS bufs ----
    {
        const int qrow = lane >> 2;
        const int qcol = (lane & 3) * 2;
#pragma unroll
        for (int mt = 0; mt < 2; mt++) {
            int r_base = wm * 32 + mt * 16 + qrow;
#pragma unroll
            for (int nt = 0; nt < 8; nt++) {
                int col = wn * 64 + nt * 8 + qcol;
                float2 ap = __ldg((const float2*)(g_aproj + a_idx * 128 + col));
#pragma unroll
                for (int hf = 0; hf < 2; hf++) {
                    int row = r_base + 8 * hf;
                    __half2 bph = *(const __half2*)(g_bprojh + (size_t)(b0 + row) * 128 + col);
                    float2 bp = __half22float2(bph);
                    float v0 = fmaxf(acc[mt][nt][2 * hf] + ap.x + bp.x, 0.f);
                    float v1 = fmaxf(acc[mt][nt][2 * hf + 1] + ap.y + bp.y, 0.f);
                    __half2 h01 = __floats2half2_rn(v0, v1);
                    int ch = col >> 6;
                    *(uint32_t*)(smem_c + AS_OFF + ch * BLK + (uint32_t)row * RSTRIDE +
                                 (col & 63) * 2) = *reinterpret_cast<uint32_t*>(&h01);
                    acc[mt][nt][2 * hf] = 0.f;
                    acc[mt][nt][2 * hf + 1] = 0.f;
                }
            }
        }
    }
    CP_WAIT_ALL();   // We2 chunks landed
    __syncthreads();

    // ================= GEMM2: h @ We2 (K=128, 2 chunks) =====================
#pragma unroll
    for (int ch = 0; ch < 2; ch++) {
#pragma unroll
        for (int ks = 0; ks < 4; ks++) {
            const uint32_t kb = ks << 5;
            const uint32_t aB = sb + AS_OFF + ch * BLK + a_loff + kb;
            const uint32_t bB = sb + BS_OFF + ch * BLK + b_loff + kb;
            uint32_t af[2][4];
            ldsm_x4(aB, af[0]);
            ldsm_x4(aB + 16 * RSTRIDE, af[1]);
#pragma unroll
            for (int np = 0; np < 4; np++) {
                uint32_t bf[4];
                ldsm_x4(bB + np * 16 * RSTRIDE, bf);
#pragma unroll
                for (int mt = 0; mt < 2; mt++) {
                    mma_f16(acc[mt][2 * np], af[mt], bf[0], bf[1]);
                    mma_f16(acc[mt][2 * np + 1], af[mt], bf[2], bf[3]);
                }
            }
        }
    }

    // ---- Epilogue 2: out = relu(D + be2); accumulate suma partials ----
    {
        float* wsumS = (float*)(smem_c + WSUM_OFF);  // [8 warps][64]
        const int qrow = lane >> 2;
        const int qc = lane & 3;
#pragma unroll
        for (int nt = 0; nt < 8; nt++) {
            int col = wn * 64 + nt * 8 + qc * 2;
            float2 bz = __ldg((const float2*)(be2 + col));
            float p0 = 0.f, p1 = 0.f;
#pragma unroll
            for (int mt = 0; mt < 2; mt++) {
                int r_base = wm * 32 + mt * 16 + qrow;
#pragma unroll
                for (int hf = 0; hf < 2; hf++) {
                    int row = r_base + 8 * hf;
                    float2 w;
                    w.x = fmaxf(acc[mt][nt][2 * hf] + bz.x, 0.f);
                    w.y = fmaxf(acc[mt][nt][2 * hf + 1] + bz.y, 0.f);
                    *(float2*)(out + (size_t)(m0 + row) * 128 + col) = w;
                    p0 += w.x;
                    p1 += w.y;
                }
            }
            p0 += __shfl_xor_sync(0xffffffffu, p0, 4);
            p0 += __shfl_xor_sync(0xffffffffu, p0, 8);
            p0 += __shfl_xor_sync(0xffffffffu, p0, 16);
            p1 += __shfl_xor_sync(0xffffffffu, p1, 4);
            p1 += __shfl_xor_sync(0xffffffffu, p1, 8);
            p1 += __shfl_xor_sync(0xffffffffu, p1, 16);
            if (lane < 4) {
                wsumS[wid * 64 + nt * 8 + lane * 2] = p0;
                wsumS[wid * 64 + nt * 8 + lane * 2 + 1] = p1;
            }
        }
        __syncthreads();
        if (tid < 128) {
            int wn2 = tid >> 6;
            int off = tid & 63;
            float s = wsumS[(0 * 2 + wn2) * 64 + off] + wsumS[(1 * 2 + wn2) * 64 + off] +
                      wsumS[(2 * 2 + wn2) * 64 + off] + wsumS[(3 * 2 + wn2) * 64 + off];
            atomicAdd(g_suma + a_idx * 128 + tid, s);
        }
    }
}

// ---------------------------------------------------------------------------
// K4: column sums (over a) -> g_sumb, 4-way split over a + atomics.
// ---------------------------------------------------------------------------
__global__ void __launch_bounds__(256) sum_b_kernel(const float* __restrict__ lat) {
    __shared__ float4 red[8][33];
    int b = blockIdx.x & (N_B - 1);
    int as = blockIdx.x >> 9;           // a-slice [as*128, as*128+128)
    int d4 = threadIdx.x & 31;
    int g = threadIdx.x >> 5;
    float x = 0.f, y = 0.f, z = 0.f, w = 0.f;
    const float4* p = (const float4*)lat + (size_t)b * 32;
    int a_end = as * 128 + 128;
    for (int a2 = as * 128 + g; a2 < a_end; a2 += 8) {
        float4 v = p[(size_t)a2 * (N_B * 32) + d4];
        x += v.x; y += v.y; z += v.z; w += v.w;
    }
    red[g][d4] = make_float4(x, y, z, w);
    __syncthreads();
    if (g == 0) {
#pragma unroll
        for (int k = 1; k < 8; k++) {
            float4 v = red[k][d4];
            x += v.x; y += v.y; z += v.z; w += v.w;
        }
        float* dst = g_sumb + b * EDGE_DIM + d4 * 4;
        atomicAdd(dst + 0, x);
        atomicAdd(dst + 1, y);
        atomicAdd(dst + 2, z);
        atomicAdd(dst + 3, w);
    }
}

// ---------------------------------------------------------------------------
// K5: node MLPs via tensor cores. Grid 16: tiles of 64 nodes
// (blk 0-7 = nodes_a, 8-15 = nodes_b). Warp tile 16x64 (wm over 4 row
// blocks of 16). A rows = [emb | suma/sumb]; B = Wn1/Wn2 fp16 images.
// ---------------------------------------------------------------------------
__global__ void __launch_bounds__(256, 2) node_gemm_kernel(const float* __restrict__ na,
                                                           const float* __restrict__ nb,
                                                           const float* __restrict__ bn1,
                                                           const float* __restrict__ bn2,
                                                           float* __restrict__ out_nodes) {
    extern __shared__ __align__(128) char smem_c[];
    const uint32_t sb = smem_u32(smem_c);
    const int tid = threadIdx.x;
    const int wid = tid >> 5;
    const int lane = tid & 31;
    const int wm = wid >> 1;
    const int wn = wid & 1;
    const int blk = blockIdx.x;

    const float* embBase;
    const float* sumBase;
    if (blk < 8) {
        embBase = na + (size_t)blk * 64 * 128;
        sumBase = g_suma + (size_t)blk * 64 * 128;
    } else {
        embBase = nb + (size_t)(blk - 8) * 64 * 128;
        sumBase = g_sumb + (size_t)(blk - 8) * 64 * 128;
    }

    const uint32_t a_loff = (uint32_t)(wm * 16 + (lane & 15)) * RSTRIDE + ((lane >> 4) << 4);
    const uint32_t b_loff = (uint32_t)(wn * 64 + (lane & 7) + ((lane >> 4) << 3)) * RSTRIDE +
                            (((lane >> 3) & 1) << 4);

    // Prologue: Wn1 chunk0
    {
        const char* src = (const char*)g_Wn1img;
#pragma unroll
        for (int i = 0; i < 4; i++) {
            int idx = tid + i * 256;
            int n = idx >> 3;
            int p = idx & 7;
            CP_ASYNC16(sb + BS_OFF + n * RSTRIDE + p * 16, src + (size_t)idx * 16);
        }
        CP_COMMIT();
    }
    float4 regsA[4];
    {
        const float* Ag = embBase;   // chunk0: emb cols 0-63, 64 rows
#pragma unroll
        for (int i = 0; i < 4; i++) {
            int idx = tid + i * 256;
            regsA[i] = *(const float4*)(Ag + (size_t)(idx >> 4) * 128 + (idx & 15) * 4);
        }
    }

    float acc[8][4];
#pragma unroll
    for (int nt = 0; nt < 8; nt++)
#pragma unroll
        for (int q = 0; q < 4; q++) acc[nt][q] = 0.f;

    // GEMM1: [emb|sum] @ Wn1 (K=256, 4 chunks)
    for (int kc = 0; kc < 4; kc++) {
        const int buf = kc & 1;
#pragma unroll
        for (int i = 0; i < 4; i++) {
            int idx = tid + i * 256;
            int row = idx >> 4;
            int f4 = idx & 15;
            float4 v = regsA[i];
            __half2 h01 = __floats2half2_rn(v.x, v.y);
            __half2 h23 = __floats2half2_rn(v.z, v.w);
            *(uint2*)(smem_c + AS_OFF + buf * BLK + (uint32_t)row * RSTRIDE + f4 * 8) =
                make_uint2(*reinterpret_cast<uint32_t*>(&h01),
                           *reinterpret_cast<uint32_t*>(&h23));
        }
        CP_WAIT_ALL();
        __syncthreads();
        if (kc < 3) {
            const char* srcB = (const char*)(g_Wn1img + (size_t)(kc + 1) * 8192);
#pragma unroll
            for (int i = 0; i < 4; i++) {
                int idx = tid + i * 256;
                int n = idx >> 3;
                int p = idx & 7;
                CP_ASYNC16(sb + BS_OFF + (buf ^ 1) * BLK + n * RSTRIDE + p * 16,
                           srcB + (size_t)idx * 16);
            }
            CP_COMMIT();
            // A chunk kc+1: 1 -> emb cols 64-127, 2/3 -> sum cols
            const float* Ag = (kc + 1 < 2) ? (embBase + 64)
                                           : (sumBase + (kc + 1 - 2) * 64);
#pragma unroll
            for (int i = 0; i < 4; i++) {
                int idx = tid + i * 256;
                regsA[i] = *(const float4*)(Ag + (size_t)(idx >> 4) * 128 + (idx & 15) * 4);
            }
        } else {
            const char* srcW = (const char*)g_Wn2img;
#pragma unroll
            for (int i = 0; i < 4; i++) {
                int idx = tid + i * 256;
                int n = idx >> 3;
                int p = idx & 7;
                CP_ASYNC16(sb + BS_OFF + 0 * BLK + n * RSTRIDE + p * 16,
                           srcW + (size_t)idx * 16);
            }
            CP_COMMIT();
        }
#pragma unroll
        for (int ks = 0; ks < 4; ks++) {
            const uint32_t kb = ks << 5;
            uint32_t af[4];
            ldsm_x4(sb + AS_OFF + buf * BLK + a_loff + kb, af);
            const uint32_t bB = sb + BS_OFF + buf * BLK + b_loff + kb;
#pragma unroll
            for (int np = 0; np < 4; np++) {
                uint32_t bf[4];
                ldsm_x4(bB + np * 16 * RSTRIDE, bf);
                mma_f16(acc[2 * np], af, bf[0], bf[1]);
                mma_f16(acc[2 * np + 1], af, bf[2], bf[3]);
            }
        }
    }
    __syncthreads();

    // Wn2 chunk1 -> BS buf1
    {
        const char* srcW = (const char*)(g_Wn2img + 8192);
#pragma unroll
        for (int i = 0; i < 4; i++) {
            int idx = tid + i * 256;
            int n = idx >> 3;
            int p = idx & 7;
            CP_ASYNC16(sb + BS_OFF + 1 * BLK + n * RSTRIDE + p * 16, srcW + (size_t)idx * 16);
        }
        CP_COMMIT();
    }

    // Epilogue 1: hmid = relu(D + bn1) -> fp16 images in AS bufs (64 rows)
    {
        const int qrow = lane >> 2;
        const int qcol = (lane & 3) * 2;
        int r_base = wm * 16 + qrow;
#pragma unroll
        for (int nt = 0; nt < 8; nt++) {
            int col = wn * 64 + nt * 8 + qcol;
            float2 bz = __ldg((const float2*)(bn1 + col));
#pragma unroll
            for (int hf = 0; hf < 2; hf++) {
                int row = r_base + 8 * hf;
                float v0 = fmaxf(acc[nt][2 * hf] + bz.x, 0.f);
                float v1 = fmaxf(acc[nt][2 * hf + 1] + bz.y, 0.f);
                __half2 h01 = __floats2half2_rn(v0, v1);
                int ch = col >> 6;
                *(uint32_t*)(smem_c + AS_OFF + ch * BLK + (uint32_t)row * RSTRIDE +
                             (col & 63) * 2) = *reinterpret_cast<uint32_t*>(&h01);
                acc[nt][2 * hf] = 0.f;
                acc[nt][2 * hf + 1] = 0.f;
            }
        }
    }
    CP_WAIT_ALL();
    __syncthreads();

    // GEMM2: hmid @ Wn2 (K=128, 2 chunks)
#pragma unroll
    for (int ch = 0; ch < 2; ch++) {
#pragma unroll
        for (int ks = 0; ks < 4; ks++) {
            const uint32_t kb = ks << 5;
            uint32_t af[4];
            ldsm_x4(sb + AS_OFF + ch * BLK + a_loff + kb, af);
            const uint32_t bB = sb + BS_OFF + ch * BLK + b_loff + kb;
#pragma unroll
            for (int np = 0; np < 4; np++) {
                uint32_t bf[4];
                ldsm_x4(bB + np * 16 * RSTRIDE, bf);
                mma_f16(acc[2 * np], af, bf[0], bf[1]);
                mma_f16(acc[2 * np + 1], af, bf[2], bf[3]);
            }
        }
    }

    // Epilogue 2: out = relu(D + bn2)
    {
        const int qrow = lane >> 2;
        const int qcol = (lane & 3) * 2;
        const int r0g = blk * 64;
        int r_base = wm * 16 + qrow;
#pragma unroll
        for (int nt = 0; nt < 8; nt++) {
            int col = wn * 64 + nt * 8 + qcol;
            float2 bz = __ldg((const float2*)(bn2 + col));
#pragma unroll
            for (int hf = 0; hf < 2; hf++) {
                int row = r_base + 8 * hf;
                float2 w;
                w.x = fmaxf(acc[nt][2 * hf] + bz.x, 0.f);
                w.y = fmaxf(acc[nt][2 * hf + 1] + bz.y, 0.f);
                *(float2*)(out_nodes + (size_t)(r0g + row) * 128 + col) = w;
            }
        }
    }
}

// ---------------------------------------------------------------------------
extern "C" void kernel_launch(void* const* d_in, const int* in_sizes, int n_in,
                              void* d_out, int out_size) {
    const float* edge = (const float*)d_in[0];
    const float* na   = (const float*)d_in[1];
    const float* nb   = (const float*)d_in[2];
    const float* We1  = (const float*)d_in[3];
    const float* be1  = (const float*)d_in[4];
    const float* We2  = (const float*)d_in[5];
    const float* be2  = (const float*)d_in[6];
    const float* Wn1  = (const float*)d_in[7];
    const float* bn1  = (const float*)d_in[8];
    const float* Wn2  = (const float*)d_in[9];
    const float* bn2  = (const float*)d_in[10];
    float* out = (float*)d_out;

    static int smem_set = 0;
    if (!smem_set) {
        cudaFuncSetAttribute(fused_kernel, cudaFuncAttributeMaxDynamicSharedMemorySize,
                             SMEM_BYTES);
        cudaFuncSetAttribute(node_gemm_kernel, cudaFuncAttributeMaxDynamicSharedMemorySize,
                             SMEM_BYTES);
        smem_set = 1;
    }

    init_kernel<<<1408, 256>>>(We1, We2, na, nb, be1, Wn1, Wn2);
    fused_kernel<<<M_EDGES / 128, 256, SMEM_BYTES>>>(edge, be2, out);
    sum_b_kernel<<<4 * N_B, 256>>>(out);
    node_gemm_kernel<<<16, 256, SMEM_BYTES>>>(na, nb, bn1, bn2,
                                              out + (size_t)M_EDGES * EDGE_DIM);
}